// round 6
// baseline (speedup 1.0000x reference)
#include <cuda_runtime.h>
#include <cuda_bf16.h>
#include <math.h>
#include <stdint.h>

#define BATCH 8
#define LQ    2048
#define SK    2048
#define DIM   128
#define BM    128
#define BN    64
#define NTHREADS 256
#define QSTRB 136            // bf16 per smem row (DIM + 8 pad) -> 272B row stride

// pre-split bf16 hi/lo scratch (hi + lo == fp32 value to ~2^-18)
__device__ __nv_bfloat16 g_qh[BATCH * LQ * DIM];
__device__ __nv_bfloat16 g_ql[BATCH * LQ * DIM];
__device__ __nv_bfloat16 g_kh[BATCH * SK * DIM];
__device__ __nv_bfloat16 g_kl[BATCH * SK * DIM];
__device__ __nv_bfloat16 g_vh[BATCH * SK * DIM];
__device__ __nv_bfloat16 g_vl[BATCH * SK * DIM];

__device__ __forceinline__ uint32_t pack2(__nv_bfloat16 a, __nv_bfloat16 b) {
    __nv_bfloat162 t; t.x = a; t.y = b;
    return *(uint32_t*)&t;
}

// normalize (Q scaled by 64) and hi/lo split, one warp per row
__global__ void prep_kernel(const float* __restrict__ q,
                            const float* __restrict__ k,
                            const float* __restrict__ v) {
    int row = blockIdx.x * 8 + (threadIdx.x >> 5);   // 0 .. 3*BATCH*2048-1
    int lane = threadIdx.x & 31;
    int kind = row / (BATCH * 2048);                  // 0=Q 1=K 2=V
    int r = row - kind * BATCH * 2048;

    const float* src = (kind == 0 ? q : kind == 1 ? k : v) + (size_t)r * DIM;
    __nv_bfloat16* dh = (kind == 0 ? g_qh : kind == 1 ? g_kh : g_vh) + (size_t)r * DIM;
    __nv_bfloat16* dl = (kind == 0 ? g_ql : kind == 1 ? g_kl : g_vl) + (size_t)r * DIM;

    float4 val = ((const float4*)src)[lane];
    if (kind < 2) {
        float ss = val.x * val.x + val.y * val.y + val.z * val.z + val.w * val.w;
#pragma unroll
        for (int off = 16; off > 0; off >>= 1)
            ss += __shfl_xor_sync(0xffffffffu, ss, off);
        float inv = (kind == 0 ? 64.0f : 1.0f) / fmaxf(sqrtf(ss), 1e-12f);
        val.x *= inv; val.y *= inv; val.z *= inv; val.w *= inv;
    }
    float f[4] = {val.x, val.y, val.z, val.w};
    __nv_bfloat16 h[4]; float rres[4];
#pragma unroll
    for (int i = 0; i < 4; i++) {
        h[i] = __float2bfloat16_rn(f[i]);
        rres[i] = f[i] - __bfloat162float(h[i]);
    }
    uint2 hv, lv;
    hv.x = pack2(h[0], h[1]);
    hv.y = pack2(h[2], h[3]);
    lv.x = pack2(__float2bfloat16_rn(rres[0]), __float2bfloat16_rn(rres[1]));
    lv.y = pack2(__float2bfloat16_rn(rres[2]), __float2bfloat16_rn(rres[3]));
    *(uint2*)(dh + lane * 4) = hv;
    *(uint2*)(dl + lane * 4) = lv;
}

__device__ __forceinline__ uint32_t smem_u32(const void* p) {
    return (uint32_t)__cvta_generic_to_shared(p);
}
__device__ __forceinline__ void cp16(uint32_t daddr, const void* g) {
    asm volatile("cp.async.cg.shared.global [%0], [%1], 16;" :: "r"(daddr), "l"(g));
}
__device__ __forceinline__ void cp_commit() {
    asm volatile("cp.async.commit_group;" ::: "memory");
}
__device__ __forceinline__ void cp_wait0() {
    asm volatile("cp.async.wait_group 0;" ::: "memory");
}
__device__ __forceinline__ void ldsm_x4(uint32_t& r0, uint32_t& r1,
                                        uint32_t& r2, uint32_t& r3, uint32_t a) {
    asm volatile("ldmatrix.sync.aligned.m8n8.x4.shared.b16 {%0,%1,%2,%3}, [%4];"
                 : "=r"(r0), "=r"(r1), "=r"(r2), "=r"(r3) : "r"(a));
}
__device__ __forceinline__ void ldsm_x4t(uint32_t& r0, uint32_t& r1,
                                         uint32_t& r2, uint32_t& r3, uint32_t a) {
    asm volatile("ldmatrix.sync.aligned.m8n8.x4.trans.shared.b16 {%0,%1,%2,%3}, [%4];"
                 : "=r"(r0), "=r"(r1), "=r"(r2), "=r"(r3) : "r"(a));
}
__device__ __forceinline__ void mma16816(float* c, uint32_t a0, uint32_t a1,
                                         uint32_t a2, uint32_t a3,
                                         uint32_t b0, uint32_t b1) {
    asm volatile(
        "mma.sync.aligned.m16n8k16.row.col.f32.bf16.bf16.f32 "
        "{%0,%1,%2,%3}, {%4,%5,%6,%7}, {%8,%9}, {%0,%1,%2,%3};"
        : "+f"(c[0]), "+f"(c[1]), "+f"(c[2]), "+f"(c[3])
        : "r"(a0), "r"(a1), "r"(a2), "r"(a3), "r"(b0), "r"(b1));
}
__device__ __forceinline__ void split2r(float x, float y, uint32_t& hi, uint32_t& lo) {
    __nv_bfloat16 hx = __float2bfloat16_rn(x);
    __nv_bfloat16 hy = __float2bfloat16_rn(y);
    hi = pack2(hx, hy);
    lo = pack2(__float2bfloat16_rn(x - __bfloat162float(hx)),
               __float2bfloat16_rn(y - __bfloat162float(hy)));
}

// smem element-offsets (bf16 units)
#define Q_ELEMS   (BM * QSTRB)          // 17408
#define KV_ARR    (BN * QSTRB)          // 8704
#define STAGE_EL  (4 * KV_ARR)          // 34816
#define STAGE0_EL (2 * Q_ELEMS)         // after Qh, Ql

__global__ __launch_bounds__(NTHREADS, 1)
void attn_kernel(float* __restrict__ out) {
    extern __shared__ __nv_bfloat16 smem[];
    const uint32_t sbase = smem_u32(smem);

    const int b    = blockIdx.y;
    const int m0   = blockIdx.x * BM;
    const int tid  = threadIdx.x;
    const int warp = tid >> 5;
    const int lane = tid & 31;
    const int g    = lane >> 2;
    const int t4   = lane & 3;

    // ---- async-load Q hi/lo tile ----
    {
        const __nv_bfloat16* gq[2] = {g_qh, g_ql};
#pragma unroll
        for (int it = 0; it < 16; it++) {
            int arr = it >> 3;                       // 2048 chunks per array
            int i = tid + it * NTHREADS;
            int within = i & 2047;
            int row = within >> 4;
            int chunk = within & 15;
            const __nv_bfloat16* gp = gq[arr] +
                ((size_t)(b * LQ + m0 + row)) * DIM + chunk * 8;
            uint32_t el = (uint32_t)(arr * Q_ELEMS + row * QSTRB + chunk * 8);
            cp16(sbase + el * 2, gp);
        }
    }
    // ---- prefetch K/V tile 0 into stage 0 ----
    {
        const __nv_bfloat16* garr[4] = {g_kh, g_kl, g_vh, g_vl};
#pragma unroll
        for (int it = 0; it < 16; it++) {
            int arr = it >> 2;                       // 1024 chunks per array
            int i = tid + it * NTHREADS;
            int within = i & 1023;
            int row = within >> 4;
            int chunk = within & 15;
            const __nv_bfloat16* gp = garr[arr] +
                ((size_t)(b * SK + row)) * DIM + chunk * 8;
            uint32_t el = (uint32_t)(STAGE0_EL + arr * KV_ARR + row * QSTRB + chunk * 8);
            cp16(sbase + el * 2, gp);
        }
    }
    cp_commit();

    float o[16][4];
    float sc[8][4];
    float m0_ = -INFINITY, m1_ = -INFINITY, l0_ = 0.0f, l1_ = 0.0f;
#pragma unroll
    for (int j = 0; j < 16; j++)
#pragma unroll
        for (int c = 0; c < 4; c++) o[j][c] = 0.0f;

    // per-thread ldmatrix byte offsets (relative to each array base)
    const uint32_t qoff = (uint32_t)(16 * warp + (lane & 15)) * (QSTRB * 2) +
                          (uint32_t)(lane >> 4) * 16;
    const uint32_t koff = (uint32_t)((lane >> 4) * 8 + (lane & 7)) * (QSTRB * 2) +
                          (uint32_t)(lane & 8) * 2;
    const uint32_t voff = (uint32_t)((lane & 8) + (lane & 7)) * (QSTRB * 2) +
                          (uint32_t)((lane & 16) >> 1) * 2;
    const uint32_t qh0 = sbase + qoff;
    const uint32_t ql0 = sbase + Q_ELEMS * 2 + qoff;

    cp_wait0();
    __syncthreads();

    int sidx = 0;
    for (int s0 = 0; s0 < SK; s0 += BN, sidx ^= 1) {
        // prefetch next tile into other stage
        if (s0 + BN < SK) {
            const __nv_bfloat16* garr[4] = {g_kh, g_kl, g_vh, g_vl};
            uint32_t stbase = (uint32_t)(STAGE0_EL + (sidx ^ 1) * STAGE_EL);
#pragma unroll
            for (int it = 0; it < 16; it++) {
                int arr = it >> 2;
                int i = tid + it * NTHREADS;
                int within = i & 1023;
                int row = within >> 4;
                int chunk = within & 15;
                const __nv_bfloat16* gp = garr[arr] +
                    ((size_t)(b * SK + s0 + BN + row)) * DIM + chunk * 8;
                uint32_t el = stbase + (uint32_t)(arr * KV_ARR + row * QSTRB + chunk * 8);
                cp16(sbase + el * 2, gp);
            }
            cp_commit();
        }

        const uint32_t stb = sbase + (uint32_t)(STAGE0_EL + sidx * STAGE_EL) * 2;
        const uint32_t kh0 = stb + koff;
        const uint32_t kl0 = stb + KV_ARR * 2 + koff;
        const uint32_t vh0 = stb + 2 * KV_ARR * 2 + voff;
        const uint32_t vl0 = stb + 3 * KV_ARR * 2 + voff;

        // ---- S = Qn Kn^T (3-pass hi/lo) ----
#pragma unroll
        for (int j = 0; j < 8; j++)
#pragma unroll
            for (int c = 0; c < 4; c++) sc[j][c] = 0.0f;

#pragma unroll
        for (int ks = 0; ks < DIM / 16; ks++) {
            uint32_t dbyte = (uint32_t)(ks * 16) * 2;
            uint32_t ah0, ah1, ah2, ah3, al0, al1, al2, al3;
            ldsm_x4(ah0, ah1, ah2, ah3, qh0 + dbyte);
            ldsm_x4(al0, al1, al2, al3, ql0 + dbyte);
#pragma unroll
            for (int jp = 0; jp < 4; jp++) {
                uint32_t nbyte = (uint32_t)(16 * jp) * (QSTRB * 2);
                uint32_t bh0, bh1, bh2, bh3, bl0, bl1, bl2, bl3;
                ldsm_x4(bh0, bh1, bh2, bh3, kh0 + nbyte + dbyte);
                ldsm_x4(bl0, bl1, bl2, bl3, kl0 + nbyte + dbyte);
                mma16816(sc[2 * jp],     ah0, ah1, ah2, ah3, bh0, bh1);
                mma16816(sc[2 * jp],     ah0, ah1, ah2, ah3, bl0, bl1);
                mma16816(sc[2 * jp],     al0, al1, al2, al3, bh0, bh1);
                mma16816(sc[2 * jp + 1], ah0, ah1, ah2, ah3, bh2, bh3);
                mma16816(sc[2 * jp + 1], ah0, ah1, ah2, ah3, bl2, bl3);
                mma16816(sc[2 * jp + 1], al0, al1, al2, al3, bh2, bh3);
            }
        }

        // ---- online softmax ----
        float rmax0 = -INFINITY, rmax1 = -INFINITY;
#pragma unroll
        for (int j = 0; j < 8; j++) {
            rmax0 = fmaxf(rmax0, fmaxf(sc[j][0], sc[j][1]));
            rmax1 = fmaxf(rmax1, fmaxf(sc[j][2], sc[j][3]));
        }
#pragma unroll
        for (int off = 1; off <= 2; off <<= 1) {
            rmax0 = fmaxf(rmax0, __shfl_xor_sync(0xffffffffu, rmax0, off));
            rmax1 = fmaxf(rmax1, __shfl_xor_sync(0xffffffffu, rmax1, off));
        }
        float mnew0 = fmaxf(m0_, rmax0);
        float mnew1 = fmaxf(m1_, rmax1);
        float rs0 = 0.0f, rs1 = 0.0f;
#pragma unroll
        for (int j = 0; j < 8; j++) {
            sc[j][0] = __expf(sc[j][0] - mnew0);
            sc[j][1] = __expf(sc[j][1] - mnew0);
            sc[j][2] = __expf(sc[j][2] - mnew1);
            sc[j][3] = __expf(sc[j][3] - mnew1);
            rs0 += sc[j][0] + sc[j][1];
            rs1 += sc[j][2] + sc[j][3];
        }
#pragma unroll
        for (int off = 1; off <= 2; off <<= 1) {
            rs0 += __shfl_xor_sync(0xffffffffu, rs0, off);
            rs1 += __shfl_xor_sync(0xffffffffu, rs1, off);
        }
        if (mnew0 > m0_) {
            float corr = __expf(m0_ - mnew0);
            l0_ = l0_ * corr + rs0;
            m0_ = mnew0;
#pragma unroll
            for (int j = 0; j < 16; j++) { o[j][0] *= corr; o[j][1] *= corr; }
        } else l0_ += rs0;
        if (mnew1 > m1_) {
            float corr = __expf(m1_ - mnew1);
            l1_ = l1_ * corr + rs1;
            m1_ = mnew1;
#pragma unroll
            for (int j = 0; j < 16; j++) { o[j][2] *= corr; o[j][3] *= corr; }
        } else l1_ += rs1;

        // ---- P fragments (hi/lo) in registers ----
        uint32_t ph[4][4], pl[4][4];
#pragma unroll
        for (int kk = 0; kk < 4; kk++) {
            int j0 = 2 * kk, j1 = 2 * kk + 1;
            split2r(sc[j0][0], sc[j0][1], ph[kk][0], pl[kk][0]);
            split2r(sc[j0][2], sc[j0][3], ph[kk][1], pl[kk][1]);
            split2r(sc[j1][0], sc[j1][1], ph[kk][2], pl[kk][2]);
            split2r(sc[j1][2], sc[j1][3], ph[kk][3], pl[kk][3]);
        }

        // ---- O += P V (3-pass hi/lo) ----
#pragma unroll
        for (int dp = 0; dp < 8; dp++) {
            uint32_t dbyte = (uint32_t)(16 * dp) * 2;
#pragma unroll
            for (int kk = 0; kk < 4; kk++) {
                uint32_t sbyte = (uint32_t)(16 * kk) * (QSTRB * 2);
                uint32_t bh0, bh1, bh2, bh3, bl0, bl1, bl2, bl3;
                ldsm_x4t(bh0, bh1, bh2, bh3, vh0 + sbyte + dbyte);
                ldsm_x4t(bl0, bl1, bl2, bl3, vl0 + sbyte + dbyte);
                mma16816(o[2 * dp], ph[kk][0], ph[kk][1], ph[kk][2], ph[kk][3], bh0, bh1);
                mma16816(o[2 * dp], ph[kk][0], ph[kk][1], ph[kk][2], ph[kk][3], bl0, bl1);
                mma16816(o[2 * dp], pl[kk][0], pl[kk][1], pl[kk][2], pl[kk][3], bh0, bh1);
                mma16816(o[2 * dp + 1], ph[kk][0], ph[kk][1], ph[kk][2], ph[kk][3], bh2, bh3);
                mma16816(o[2 * dp + 1], ph[kk][0], ph[kk][1], ph[kk][2], ph[kk][3], bl2, bl3);
                mma16816(o[2 * dp + 1], pl[kk][0], pl[kk][1], pl[kk][2], pl[kk][3], bh2, bh3);
            }
        }

        cp_wait0();
        __syncthreads();
    }

    // ---- epilogue ----
    float inv0 = 1.0f / l0_;
    float inv1 = 1.0f / l1_;
    int r0 = m0 + 16 * warp + g;
    float* ob0 = out + ((size_t)b * LQ + r0) * DIM;
    float* ob1 = ob0 + 8 * DIM;
#pragma unroll
    for (int j = 0; j < 16; j++) {
        int c = 8 * j + 2 * t4;
        *(float2*)(ob0 + c) = make_float2(o[j][0] * inv0, o[j][1] * inv0);
        *(float2*)(ob1 + c) = make_float2(o[j][2] * inv1, o[j][3] * inv1);
    }
}

extern "C" void kernel_launch(void* const* d_in, const int* in_sizes, int n_in,
                              void* d_out, int out_size) {
    const float* q = (const float*)d_in[0];
    const float* k = (const float*)d_in[1];
    const float* v = (const float*)d_in[2];
    float* out = (float*)d_out;

    prep_kernel<<<(3 * BATCH * 2048) / 8, 256>>>(q, k, v);

    size_t smem_bytes = (size_t)(2 * Q_ELEMS + 2 * STAGE_EL) * sizeof(__nv_bfloat16);
    cudaFuncSetAttribute(attn_kernel,
                         cudaFuncAttributeMaxDynamicSharedMemorySize,
                         (int)smem_bytes);
    dim3 grid(LQ / BM, BATCH);
    attn_kernel<<<grid, NTHREADS, smem_bytes>>>(out);
}

// round 7
// speedup vs baseline: 1.3623x; 1.3623x over previous
#include <cuda_runtime.h>
#include <cuda_bf16.h>
#include <math.h>
#include <stdint.h>

#define BATCH 8
#define LQ    2048
#define SK    2048
#define DIM   128
#define BM    64
#define BN    64
#define NTHREADS 128
#define QSTRB 136            // bf16 per smem row (DIM + 8 pad)

// pre-split bf16 hi/lo scratch (hi + lo == fp32 value to ~2^-18)
__device__ __nv_bfloat16 g_qh[BATCH * LQ * DIM];
__device__ __nv_bfloat16 g_ql[BATCH * LQ * DIM];
__device__ __nv_bfloat16 g_kh[BATCH * SK * DIM];
__device__ __nv_bfloat16 g_kl[BATCH * SK * DIM];
__device__ __nv_bfloat16 g_vh[BATCH * SK * DIM];
__device__ __nv_bfloat16 g_vl[BATCH * SK * DIM];

__device__ __forceinline__ uint32_t pack2(__nv_bfloat16 a, __nv_bfloat16 b) {
    __nv_bfloat162 t; t.x = a; t.y = b;
    return *(uint32_t*)&t;
}

// normalize (Q scaled by 64) and hi/lo split, one warp per row
__global__ void prep_kernel(const float* __restrict__ q,
                            const float* __restrict__ k,
                            const float* __restrict__ v) {
    int row = blockIdx.x * 8 + (threadIdx.x >> 5);
    int lane = threadIdx.x & 31;
    int kind = row / (BATCH * 2048);                  // 0=Q 1=K 2=V
    int r = row - kind * BATCH * 2048;

    const float* src = (kind == 0 ? q : kind == 1 ? k : v) + (size_t)r * DIM;
    __nv_bfloat16* dh = (kind == 0 ? g_qh : kind == 1 ? g_kh : g_vh) + (size_t)r * DIM;
    __nv_bfloat16* dl = (kind == 0 ? g_ql : kind == 1 ? g_kl : g_vl) + (size_t)r * DIM;

    float4 val = ((const float4*)src)[lane];
    if (kind < 2) {
        float ss = val.x * val.x + val.y * val.y + val.z * val.z + val.w * val.w;
#pragma unroll
        for (int off = 16; off > 0; off >>= 1)
            ss += __shfl_xor_sync(0xffffffffu, ss, off);
        float inv = (kind == 0 ? 64.0f : 1.0f) / fmaxf(sqrtf(ss), 1e-12f);
        val.x *= inv; val.y *= inv; val.z *= inv; val.w *= inv;
    }
    float f[4] = {val.x, val.y, val.z, val.w};
    __nv_bfloat16 h[4]; float rres[4];
#pragma unroll
    for (int i = 0; i < 4; i++) {
        h[i] = __float2bfloat16_rn(f[i]);
        rres[i] = f[i] - __bfloat162float(h[i]);
    }
    uint2 hv, lv;
    hv.x = pack2(h[0], h[1]);
    hv.y = pack2(h[2], h[3]);
    lv.x = pack2(__float2bfloat16_rn(rres[0]), __float2bfloat16_rn(rres[1]));
    lv.y = pack2(__float2bfloat16_rn(rres[2]), __float2bfloat16_rn(rres[3]));
    *(uint2*)(dh + lane * 4) = hv;
    *(uint2*)(dl + lane * 4) = lv;
}

__device__ __forceinline__ uint32_t smem_u32(const void* p) {
    return (uint32_t)__cvta_generic_to_shared(p);
}
__device__ __forceinline__ void cp16(uint32_t daddr, const void* g) {
    asm volatile("cp.async.cg.shared.global [%0], [%1], 16;" :: "r"(daddr), "l"(g));
}
__device__ __forceinline__ void cp_commit() {
    asm volatile("cp.async.commit_group;" ::: "memory");
}
__device__ __forceinline__ void cp_wait0() {
    asm volatile("cp.async.wait_group 0;" ::: "memory");
}
__device__ __forceinline__ void ldsm_x4(uint32_t& r0, uint32_t& r1,
                                        uint32_t& r2, uint32_t& r3, uint32_t a) {
    asm volatile("ldmatrix.sync.aligned.m8n8.x4.shared.b16 {%0,%1,%2,%3}, [%4];"
                 : "=r"(r0), "=r"(r1), "=r"(r2), "=r"(r3) : "r"(a));
}
__device__ __forceinline__ void ldsm_x4t(uint32_t& r0, uint32_t& r1,
                                         uint32_t& r2, uint32_t& r3, uint32_t a) {
    asm volatile("ldmatrix.sync.aligned.m8n8.x4.trans.shared.b16 {%0,%1,%2,%3}, [%4];"
                 : "=r"(r0), "=r"(r1), "=r"(r2), "=r"(r3) : "r"(a));
}
__device__ __forceinline__ void mma16816(float* c, uint32_t a0, uint32_t a1,
                                         uint32_t a2, uint32_t a3,
                                         uint32_t b0, uint32_t b1) {
    asm volatile(
        "mma.sync.aligned.m16n8k16.row.col.f32.bf16.bf16.f32 "
        "{%0,%1,%2,%3}, {%4,%5,%6,%7}, {%8,%9}, {%0,%1,%2,%3};"
        : "+f"(c[0]), "+f"(c[1]), "+f"(c[2]), "+f"(c[3])
        : "r"(a0), "r"(a1), "r"(a2), "r"(a3), "r"(b0), "r"(b1));
}
__device__ __forceinline__ void split2r(float x, float y, uint32_t& hi, uint32_t& lo) {
    __nv_bfloat16 hx = __float2bfloat16_rn(x);
    __nv_bfloat16 hy = __float2bfloat16_rn(y);
    hi = pack2(hx, hy);
    lo = pack2(__float2bfloat16_rn(x - __bfloat162float(hx)),
               __float2bfloat16_rn(y - __bfloat162float(hy)));
}

// smem element-offsets (bf16 units)
#define Q_ELEMS   (BM * QSTRB)          // 8704
#define KV_ARR    (BN * QSTRB)          // 8704
#define KV0_EL    (2 * Q_ELEMS)         // after Qh, Ql

__global__ __launch_bounds__(NTHREADS, 2)
void attn_kernel(float* __restrict__ out) {
    extern __shared__ __nv_bfloat16 smem[];
    const uint32_t sbase = smem_u32(smem);

    const int b    = blockIdx.y;
    const int m0   = blockIdx.x * BM;
    const int tid  = threadIdx.x;
    const int warp = tid >> 5;        // 0..3
    const int lane = tid & 31;
    const int g    = lane >> 2;
    const int t4   = lane & 3;

    // ---- async-load Q hi/lo tile (2 arrays x 64 rows x 16 chunks) ----
    {
        const __nv_bfloat16* gq[2] = {g_qh, g_ql};
#pragma unroll
        for (int it = 0; it < 16; it++) {
            int i = tid + it * NTHREADS;
            int arr = i >> 10;
            int within = i & 1023;
            int row = within >> 4;
            int chunk = within & 15;
            const __nv_bfloat16* gp = gq[arr] +
                ((size_t)(b * LQ + m0 + row)) * DIM + chunk * 8;
            uint32_t el = (uint32_t)(arr * Q_ELEMS + row * QSTRB + chunk * 8);
            cp16(sbase + el * 2, gp);
        }
    }

    float o[16][4];
    float sc[8][4];
    float m0_ = -INFINITY, m1_ = -INFINITY, l0_ = 0.0f, l1_ = 0.0f;
#pragma unroll
    for (int j = 0; j < 16; j++)
#pragma unroll
        for (int c = 0; c < 4; c++) o[j][c] = 0.0f;

    // per-thread ldmatrix byte offsets
    const uint32_t qoff = (uint32_t)(16 * warp + (lane & 15)) * (QSTRB * 2) +
                          (uint32_t)(lane >> 4) * 16;
    const uint32_t koff = (uint32_t)((lane >> 4) * 8 + (lane & 7)) * (QSTRB * 2) +
                          (uint32_t)(lane & 8) * 2;
    const uint32_t voff = (uint32_t)((lane & 8) + (lane & 7)) * (QSTRB * 2) +
                          (uint32_t)((lane & 16) >> 1) * 2;
    const uint32_t qh0 = sbase + qoff;
    const uint32_t ql0 = sbase + Q_ELEMS * 2 + qoff;
    const uint32_t kh0 = sbase + KV0_EL * 2 + koff;
    const uint32_t kl0 = sbase + (KV0_EL + KV_ARR) * 2 + koff;
    const uint32_t vh0 = sbase + (KV0_EL + 2 * KV_ARR) * 2 + voff;
    const uint32_t vl0 = sbase + (KV0_EL + 3 * KV_ARR) * 2 + voff;

    const __nv_bfloat16* garr[4] = {g_kh, g_kl, g_vh, g_vl};

    for (int s0 = 0; s0 < SK; s0 += BN) {
        if (s0) __syncthreads();   // all warps done reading previous K/V
        // ---- load K/V tile (4 arrays x 64 rows x 16 chunks) ----
#pragma unroll
        for (int it = 0; it < 32; it++) {
            int i = tid + it * NTHREADS;
            int arr = i >> 10;
            int within = i & 1023;
            int row = within >> 4;
            int chunk = within & 15;
            const __nv_bfloat16* gp = garr[arr] +
                ((size_t)(b * SK + s0 + row)) * DIM + chunk * 8;
            uint32_t el = (uint32_t)(KV0_EL + arr * KV_ARR + row * QSTRB + chunk * 8);
            cp16(sbase + el * 2, gp);
        }
        cp_commit();
        cp_wait0();
        __syncthreads();

        // ---- S = Qn Kn^T (3-pass hi/lo) ----
#pragma unroll
        for (int j = 0; j < 8; j++)
#pragma unroll
            for (int c = 0; c < 4; c++) sc[j][c] = 0.0f;

#pragma unroll
        for (int ks = 0; ks < DIM / 16; ks++) {
            uint32_t dbyte = (uint32_t)(ks * 16) * 2;
            uint32_t ah0, ah1, ah2, ah3, al0, al1, al2, al3;
            ldsm_x4(ah0, ah1, ah2, ah3, qh0 + dbyte);
            ldsm_x4(al0, al1, al2, al3, ql0 + dbyte);
#pragma unroll
            for (int jp = 0; jp < 4; jp++) {
                uint32_t nbyte = (uint32_t)(16 * jp) * (QSTRB * 2);
                uint32_t bh0, bh1, bh2, bh3, bl0, bl1, bl2, bl3;
                ldsm_x4(bh0, bh1, bh2, bh3, kh0 + nbyte + dbyte);
                ldsm_x4(bl0, bl1, bl2, bl3, kl0 + nbyte + dbyte);
                mma16816(sc[2 * jp],     ah0, ah1, ah2, ah3, bh0, bh1);
                mma16816(sc[2 * jp],     ah0, ah1, ah2, ah3, bl0, bl1);
                mma16816(sc[2 * jp],     al0, al1, al2, al3, bh0, bh1);
                mma16816(sc[2 * jp + 1], ah0, ah1, ah2, ah3, bh2, bh3);
                mma16816(sc[2 * jp + 1], ah0, ah1, ah2, ah3, bl2, bl3);
                mma16816(sc[2 * jp + 1], al0, al1, al2, al3, bh2, bh3);
            }
        }

        // ---- online softmax ----
        float rmax0 = -INFINITY, rmax1 = -INFINITY;
#pragma unroll
        for (int j = 0; j < 8; j++) {
            rmax0 = fmaxf(rmax0, fmaxf(sc[j][0], sc[j][1]));
            rmax1 = fmaxf(rmax1, fmaxf(sc[j][2], sc[j][3]));
        }
#pragma unroll
        for (int off = 1; off <= 2; off <<= 1) {
            rmax0 = fmaxf(rmax0, __shfl_xor_sync(0xffffffffu, rmax0, off));
            rmax1 = fmaxf(rmax1, __shfl_xor_sync(0xffffffffu, rmax1, off));
        }
        float mnew0 = fmaxf(m0_, rmax0);
        float mnew1 = fmaxf(m1_, rmax1);
        float rs0 = 0.0f, rs1 = 0.0f;
#pragma unroll
        for (int j = 0; j < 8; j++) {
            sc[j][0] = __expf(sc[j][0] - mnew0);
            sc[j][1] = __expf(sc[j][1] - mnew0);
            sc[j][2] = __expf(sc[j][2] - mnew1);
            sc[j][3] = __expf(sc[j][3] - mnew1);
            rs0 += sc[j][0] + sc[j][1];
            rs1 += sc[j][2] + sc[j][3];
        }
#pragma unroll
        for (int off = 1; off <= 2; off <<= 1) {
            rs0 += __shfl_xor_sync(0xffffffffu, rs0, off);
            rs1 += __shfl_xor_sync(0xffffffffu, rs1, off);
        }
        if (mnew0 > m0_) {
            float corr = __expf(m0_ - mnew0);
            l0_ = l0_ * corr + rs0;
            m0_ = mnew0;
#pragma unroll
            for (int j = 0; j < 16; j++) { o[j][0] *= corr; o[j][1] *= corr; }
        } else l0_ += rs0;
        if (mnew1 > m1_) {
            float corr = __expf(m1_ - mnew1);
            l1_ = l1_ * corr + rs1;
            m1_ = mnew1;
#pragma unroll
            for (int j = 0; j < 16; j++) { o[j][2] *= corr; o[j][3] *= corr; }
        } else l1_ += rs1;

        // ---- P fragments (hi/lo) in registers ----
        uint32_t ph[4][4], pl[4][4];
#pragma unroll
        for (int kk = 0; kk < 4; kk++) {
            int j0 = 2 * kk, j1 = 2 * kk + 1;
            split2r(sc[j0][0], sc[j0][1], ph[kk][0], pl[kk][0]);
            split2r(sc[j0][2], sc[j0][3], ph[kk][1], pl[kk][1]);
            split2r(sc[j1][0], sc[j1][1], ph[kk][2], pl[kk][2]);
            split2r(sc[j1][2], sc[j1][3], ph[kk][3], pl[kk][3]);
        }

        // ---- O += P V (3-pass hi/lo) ----
#pragma unroll
        for (int dp = 0; dp < 8; dp++) {
            uint32_t dbyte = (uint32_t)(16 * dp) * 2;
#pragma unroll
            for (int kk = 0; kk < 4; kk++) {
                uint32_t sbyte = (uint32_t)(16 * kk) * (QSTRB * 2);
                uint32_t bh0, bh1, bh2, bh3, bl0, bl1, bl2, bl3;
                ldsm_x4t(bh0, bh1, bh2, bh3, vh0 + sbyte + dbyte);
                ldsm_x4t(bl0, bl1, bl2, bl3, vl0 + sbyte + dbyte);
                mma16816(o[2 * dp], ph[kk][0], ph[kk][1], ph[kk][2], ph[kk][3], bh0, bh1);
                mma16816(o[2 * dp], ph[kk][0], ph[kk][1], ph[kk][2], ph[kk][3], bl0, bl1);
                mma16816(o[2 * dp], pl[kk][0], pl[kk][1], pl[kk][2], pl[kk][3], bh0, bh1);
                mma16816(o[2 * dp + 1], ph[kk][0], ph[kk][1], ph[kk][2], ph[kk][3], bh2, bh3);
                mma16816(o[2 * dp + 1], ph[kk][0], ph[kk][1], ph[kk][2], ph[kk][3], bl2, bl3);
                mma16816(o[2 * dp + 1], pl[kk][0], pl[kk][1], pl[kk][2], pl[kk][3], bh2, bh3);
            }
        }
    }

    // ---- epilogue ----
    float inv0 = 1.0f / l0_;
    float inv1 = 1.0f / l1_;
    int r0 = m0 + 16 * warp + g;
    float* ob0 = out + ((size_t)b * LQ + r0) * DIM;
    float* ob1 = ob0 + 8 * DIM;
#pragma unroll
    for (int j = 0; j < 16; j++) {
        int c = 8 * j + 2 * t4;
        *(float2*)(ob0 + c) = make_float2(o[j][0] * inv0, o[j][1] * inv0);
        *(float2*)(ob1 + c) = make_float2(o[j][2] * inv1, o[j][3] * inv1);
    }
}

extern "C" void kernel_launch(void* const* d_in, const int* in_sizes, int n_in,
                              void* d_out, int out_size) {
    const float* q = (const float*)d_in[0];
    const float* k = (const float*)d_in[1];
    const float* v = (const float*)d_in[2];
    float* out = (float*)d_out;

    prep_kernel<<<(3 * BATCH * 2048) / 8, 256>>>(q, k, v);

    size_t smem_bytes = (size_t)(2 * Q_ELEMS + 4 * KV_ARR) * sizeof(__nv_bfloat16);
    cudaFuncSetAttribute(attn_kernel,
                         cudaFuncAttributeMaxDynamicSharedMemorySize,
                         (int)smem_bytes);
    dim3 grid(LQ / BM, BATCH);
    attn_kernel<<<grid, NTHREADS, smem_bytes>>>(out);
}

// round 9
// speedup vs baseline: 1.5759x; 1.1568x over previous
#include <cuda_runtime.h>
#include <cuda_bf16.h>
#include <cuda_fp16.h>
#include <math.h>
#include <stdint.h>

#define BATCH 8
#define LQ    2048
#define SK    2048
#define DIM   128
#define BM    128
#define BN    64
#define NTHREADS 256
#define QSTRB 136            // elems per smem row (DIM + 8 pad), 2B each

// pre-split scratch: Q/K bf16 hi/lo (hi+lo == fp32 to ~2^-18), V fp16 hi/lo (~2^-24)
__device__ __nv_bfloat16 g_qh[BATCH * LQ * DIM];
__device__ __nv_bfloat16 g_ql[BATCH * LQ * DIM];
__device__ __nv_bfloat16 g_kh[BATCH * SK * DIM];
__device__ __nv_bfloat16 g_kl[BATCH * SK * DIM];
__device__ __half        g_vh[BATCH * SK * DIM];
__device__ __half        g_vl[BATCH * SK * DIM];

__device__ __forceinline__ uint32_t pack2(__nv_bfloat16 a, __nv_bfloat16 b) {
    __nv_bfloat162 t; t.x = a; t.y = b;
    return *(uint32_t*)&t;
}
__device__ __forceinline__ uint32_t pack2h(__half a, __half b) {
    __half2 t; t.x = a; t.y = b;
    return *(uint32_t*)&t;
}

// normalize (Q scaled by 64) and split, one warp per row
__global__ void prep_kernel(const float* __restrict__ q,
                            const float* __restrict__ k,
                            const float* __restrict__ v) {
    int row = blockIdx.x * 8 + (threadIdx.x >> 5);
    int lane = threadIdx.x & 31;
    int kind = row / (BATCH * 2048);                  // 0=Q 1=K 2=V
    int r = row - kind * BATCH * 2048;

    const float* src = (kind == 0 ? q : kind == 1 ? k : v) + (size_t)r * DIM;

    float4 val = ((const float4*)src)[lane];
    if (kind < 2) {
        float ss = val.x * val.x + val.y * val.y + val.z * val.z + val.w * val.w;
#pragma unroll
        for (int off = 16; off > 0; off >>= 1)
            ss += __shfl_xor_sync(0xffffffffu, ss, off);
        float inv = (kind == 0 ? 64.0f : 1.0f) / fmaxf(sqrtf(ss), 1e-12f);
        val.x *= inv; val.y *= inv; val.z *= inv; val.w *= inv;
    }
    float f[4] = {val.x, val.y, val.z, val.w};

    if (kind < 2) {
        __nv_bfloat16* dh = (kind == 0 ? g_qh : g_kh) + (size_t)r * DIM;
        __nv_bfloat16* dl = (kind == 0 ? g_ql : g_kl) + (size_t)r * DIM;
        __nv_bfloat16 h[4]; float rres[4];
#pragma unroll
        for (int i = 0; i < 4; i++) {
            h[i] = __float2bfloat16_rn(f[i]);
            rres[i] = f[i] - __bfloat162float(h[i]);
        }
        uint2 hv, lv;
        hv.x = pack2(h[0], h[1]);
        hv.y = pack2(h[2], h[3]);
        lv.x = pack2(__float2bfloat16_rn(rres[0]), __float2bfloat16_rn(rres[1]));
        lv.y = pack2(__float2bfloat16_rn(rres[2]), __float2bfloat16_rn(rres[3]));
        *(uint2*)(dh + lane * 4) = hv;
        *(uint2*)(dl + lane * 4) = lv;
    } else {
        __half* dh = g_vh + (size_t)r * DIM;
        __half* dl = g_vl + (size_t)r * DIM;
        __half h[4]; float rres[4];
#pragma unroll
        for (int i = 0; i < 4; i++) {
            h[i] = __float2half_rn(f[i]);
            rres[i] = f[i] - __half2float(h[i]);
        }
        uint2 hv, lv;
        hv.x = pack2h(h[0], h[1]);
        hv.y = pack2h(h[2], h[3]);
        lv.x = pack2h(__float2half_rn(rres[0]), __float2half_rn(rres[1]));
        lv.y = pack2h(__float2half_rn(rres[2]), __float2half_rn(rres[3]));
        *(uint2*)(dh + lane * 4) = hv;
        *(uint2*)(dl + lane * 4) = lv;
    }
}

__device__ __forceinline__ uint32_t smem_u32(const void* p) {
    return (uint32_t)__cvta_generic_to_shared(p);
}
__device__ __forceinline__ void cp16(uint32_t daddr, const void* g) {
    asm volatile("cp.async.cg.shared.global [%0], [%1], 16;" :: "r"(daddr), "l"(g));
}
__device__ __forceinline__ void cp_commit() {
    asm volatile("cp.async.commit_group;" ::: "memory");
}
__device__ __forceinline__ void cp_wait0() {
    asm volatile("cp.async.wait_group 0;" ::: "memory");
}
__device__ __forceinline__ void ldsm_x4(uint32_t& r0, uint32_t& r1,
                                        uint32_t& r2, uint32_t& r3, uint32_t a) {
    asm volatile("ldmatrix.sync.aligned.m8n8.x4.shared.b16 {%0,%1,%2,%3}, [%4];"
                 : "=r"(r0), "=r"(r1), "=r"(r2), "=r"(r3) : "r"(a));
}
__device__ __forceinline__ void ldsm_x4t(uint32_t& r0, uint32_t& r1,
                                         uint32_t& r2, uint32_t& r3, uint32_t a) {
    asm volatile("ldmatrix.sync.aligned.m8n8.x4.trans.shared.b16 {%0,%1,%2,%3}, [%4];"
                 : "=r"(r0), "=r"(r1), "=r"(r2), "=r"(r3) : "r"(a));
}
__device__ __forceinline__ void mma_bf16(float* c, uint32_t a0, uint32_t a1,
                                         uint32_t a2, uint32_t a3,
                                         uint32_t b0, uint32_t b1) {
    asm volatile(
        "mma.sync.aligned.m16n8k16.row.col.f32.bf16.bf16.f32 "
        "{%0,%1,%2,%3}, {%4,%5,%6,%7}, {%8,%9}, {%0,%1,%2,%3};"
        : "+f"(c[0]), "+f"(c[1]), "+f"(c[2]), "+f"(c[3])
        : "r"(a0), "r"(a1), "r"(a2), "r"(a3), "r"(b0), "r"(b1));
}
__device__ __forceinline__ void mma_f16(float* c, uint32_t a0, uint32_t a1,
                                        uint32_t a2, uint32_t a3,
                                        uint32_t b0, uint32_t b1) {
    asm volatile(
        "mma.sync.aligned.m16n8k16.row.col.f32.f16.f16.f32 "
        "{%0,%1,%2,%3}, {%4,%5,%6,%7}, {%8,%9}, {%0,%1,%2,%3};"
        : "+f"(c[0]), "+f"(c[1]), "+f"(c[2]), "+f"(c[3])
        : "r"(a0), "r"(a1), "r"(a2), "r"(a3), "r"(b0), "r"(b1));
}
__device__ __forceinline__ uint32_t packh2(float x, float y) {
    __half2 t = __float22half2_rn(make_float2(x, y));
    return *(uint32_t*)&t;
}

// smem element-offsets (2-byte units)
#define Q_ELEMS   (BM * QSTRB)          // 17408
#define KV_ARR    (BN * QSTRB)          // 8704

__global__ __launch_bounds__(NTHREADS, 1)
void attn_kernel(float* __restrict__ out) {
    extern __shared__ __nv_bfloat16 smem[];
    const uint32_t sbase = smem_u32(smem);
    __nv_bfloat16* Qh = smem;
    __nv_bfloat16* Ql = Qh + Q_ELEMS;
    __nv_bfloat16* Kh = Ql + Q_ELEMS;
    __nv_bfloat16* Kl = Kh + KV_ARR;
    __half*        Vh = (__half*)(Kl + KV_ARR);
    __half*        Vl = Vh + KV_ARR;

    const int b    = blockIdx.y;
    const int m0   = blockIdx.x * BM;
    const int tid  = threadIdx.x;
    const int warp = tid >> 5;
    const int lane = tid & 31;
    const int g    = lane >> 2;
    const int t4   = lane & 3;

    // ---- async-load + no-split copy of pre-split Q hi/lo tile ----
    {
        const __nv_bfloat16* gq[2] = {g_qh, g_ql};
#pragma unroll
        for (int it = 0; it < 16; it++) {
            int arr = it >> 3;
            int i = tid + it * NTHREADS;
            int within = i & 2047;
            int row = within >> 4;
            int chunk = within & 15;
            const __nv_bfloat16* gp = gq[arr] +
                ((size_t)(b * LQ + m0 + row)) * DIM + chunk * 8;
            uint32_t el = (uint32_t)(arr * Q_ELEMS + row * QSTRB + chunk * 8);
            cp16(sbase + el * 2, gp);
        }
    }
    cp_commit();

    float o[16][4];
    float sc[8][4];
    float m0_ = -INFINITY, m1_ = -INFINITY, l0_ = 0.0f, l1_ = 0.0f;
#pragma unroll
    for (int j = 0; j < 16; j++)
#pragma unroll
        for (int c = 0; c < 4; c++) o[j][c] = 0.0f;

    // per-thread ldmatrix byte offsets
    const uint32_t qoff = (uint32_t)(16 * warp + (lane & 15)) * (QSTRB * 2) +
                          (uint32_t)(lane >> 4) * 16;
    const uint32_t koff = (uint32_t)((lane >> 4) * 8 + (lane & 7)) * (QSTRB * 2) +
                          (uint32_t)(lane & 8) * 2;
    const uint32_t voff = (uint32_t)((lane & 8) + (lane & 7)) * (QSTRB * 2) +
                          (uint32_t)((lane & 16) >> 1) * 2;
    const uint32_t qh0 = sbase + qoff;
    const uint32_t ql0 = sbase + Q_ELEMS * 2 + qoff;
    const uint32_t kh0 = sbase + 2 * Q_ELEMS * 2 + koff;
    const uint32_t kl0 = sbase + (2 * Q_ELEMS + KV_ARR) * 2 + koff;
    const uint32_t vh0 = sbase + (2 * Q_ELEMS + 2 * KV_ARR) * 2 + voff;
    const uint32_t vl0 = sbase + (2 * Q_ELEMS + 3 * KV_ARR) * 2 + voff;

    const void* garr[4] = {g_kh, g_kl, g_vh, g_vl};

    for (int s0 = 0; s0 < SK; s0 += BN) {
        if (s0) __syncthreads();   // all warps done reading previous K/V
        // ---- load K/V tile ----
#pragma unroll
        for (int it = 0; it < 16; it++) {
            int i = tid + it * NTHREADS;
            int arr = i >> 10;
            int within = i & 1023;
            int row = within >> 4;
            int chunk = within & 15;
            const char* gp = (const char*)garr[arr] +
                (((size_t)(b * SK + s0 + row)) * DIM + chunk * 8) * 2;
            uint32_t el = (uint32_t)(2 * Q_ELEMS + arr * KV_ARR + row * QSTRB + chunk * 8);
            cp16(sbase + el * 2, gp);
        }
        cp_commit();
        cp_wait0();
        __syncthreads();

        // ---- S = Qn Kn^T (3-pass bf16 hi/lo) ----
#pragma unroll
        for (int j = 0; j < 8; j++)
#pragma unroll
            for (int c = 0; c < 4; c++) sc[j][c] = 0.0f;

#pragma unroll
        for (int ks = 0; ks < DIM / 16; ks++) {
            uint32_t dbyte = (uint32_t)(ks * 16) * 2;
            uint32_t ah0, ah1, ah2, ah3, al0, al1, al2, al3;
            ldsm_x4(ah0, ah1, ah2, ah3, qh0 + dbyte);
            ldsm_x4(al0, al1, al2, al3, ql0 + dbyte);
#pragma unroll
            for (int jp = 0; jp < 4; jp++) {
                uint32_t nbyte = (uint32_t)(16 * jp) * (QSTRB * 2);
                uint32_t bh0, bh1, bh2, bh3, bl0, bl1, bl2, bl3;
                ldsm_x4(bh0, bh1, bh2, bh3, kh0 + nbyte + dbyte);
                ldsm_x4(bl0, bl1, bl2, bl3, kl0 + nbyte + dbyte);
                mma_bf16(sc[2 * jp],     ah0, ah1, ah2, ah3, bh0, bh1);
                mma_bf16(sc[2 * jp],     ah0, ah1, ah2, ah3, bl0, bl1);
                mma_bf16(sc[2 * jp],     al0, al1, al2, al3, bh0, bh1);
                mma_bf16(sc[2 * jp + 1], ah0, ah1, ah2, ah3, bh2, bh3);
                mma_bf16(sc[2 * jp + 1], ah0, ah1, ah2, ah3, bl2, bl3);
                mma_bf16(sc[2 * jp + 1], al0, al1, al2, al3, bh2, bh3);
            }
        }

        // ---- online softmax ----
        float rmax0 = -INFINITY, rmax1 = -INFINITY;
#pragma unroll
        for (int j = 0; j < 8; j++) {
            rmax0 = fmaxf(rmax0, fmaxf(sc[j][0], sc[j][1]));
            rmax1 = fmaxf(rmax1, fmaxf(sc[j][2], sc[j][3]));
        }
#pragma unroll
        for (int off = 1; off <= 2; off <<= 1) {
            rmax0 = fmaxf(rmax0, __shfl_xor_sync(0xffffffffu, rmax0, off));
            rmax1 = fmaxf(rmax1, __shfl_xor_sync(0xffffffffu, rmax1, off));
        }
        float mnew0 = fmaxf(m0_, rmax0);
        float mnew1 = fmaxf(m1_, rmax1);
        float rs0 = 0.0f, rs1 = 0.0f;
#pragma unroll
        for (int j = 0; j < 8; j++) {
            sc[j][0] = __expf(sc[j][0] - mnew0);
            sc[j][1] = __expf(sc[j][1] - mnew0);
            sc[j][2] = __expf(sc[j][2] - mnew1);
            sc[j][3] = __expf(sc[j][3] - mnew1);
            rs0 += sc[j][0] + sc[j][1];
            rs1 += sc[j][2] + sc[j][3];
        }
#pragma unroll
        for (int off = 1; off <= 2; off <<= 1) {
            rs0 += __shfl_xor_sync(0xffffffffu, rs0, off);
            rs1 += __shfl_xor_sync(0xffffffffu, rs1, off);
        }
        if (mnew0 > m0_) {
            float corr = __expf(m0_ - mnew0);
            l0_ = l0_ * corr + rs0;
            m0_ = mnew0;
#pragma unroll
            for (int j = 0; j < 16; j++) { o[j][0] *= corr; o[j][1] *= corr; }
        } else l0_ += rs0;
        if (mnew1 > m1_) {
            float corr = __expf(m1_ - mnew1);
            l1_ = l1_ * corr + rs1;
            m1_ = mnew1;
#pragma unroll
            for (int j = 0; j < 16; j++) { o[j][2] *= corr; o[j][3] *= corr; }
        } else l1_ += rs1;

        // ---- P fragments: single fp16 (exact enough; p in (0,1]) ----
        uint32_t ph[4][4];
#pragma unroll
        for (int kk = 0; kk < 4; kk++) {
            int j0 = 2 * kk, j1 = 2 * kk + 1;
            ph[kk][0] = packh2(sc[j0][0], sc[j0][1]);
            ph[kk][1] = packh2(sc[j0][2], sc[j0][3]);
            ph[kk][2] = packh2(sc[j1][0], sc[j1][1]);
            ph[kk][3] = packh2(sc[j1][2], sc[j1][3]);
        }

        // ---- O += P V (fp16 2-pass: ph*vh + ph*vl) ----
#pragma unroll
        for (int dp = 0; dp < 8; dp++) {
            uint32_t dbyte = (uint32_t)(16 * dp) * 2;
#pragma unroll
            for (int kk = 0; kk < 4; kk++) {
                uint32_t sbyte = (uint32_t)(16 * kk) * (QSTRB * 2);
                uint32_t bh0, bh1, bh2, bh3, bl0, bl1, bl2, bl3;
                ldsm_x4t(bh0, bh1, bh2, bh3, vh0 + sbyte + dbyte);
                ldsm_x4t(bl0, bl1, bl2, bl3, vl0 + sbyte + dbyte);
                mma_f16(o[2 * dp],     ph[kk][0], ph[kk][1], ph[kk][2], ph[kk][3], bh0, bh1);
                mma_f16(o[2 * dp],     ph[kk][0], ph[kk][1], ph[kk][2], ph[kk][3], bl0, bl1);
                mma_f16(o[2 * dp + 1], ph[kk][0], ph[kk][1], ph[kk][2], ph[kk][3], bh2, bh3);
                mma_f16(o[2 * dp + 1], ph[kk][0], ph[kk][1], ph[kk][2], ph[kk][3], bl2, bl3);
            }
        }
    }

    // ---- epilogue ----
    float inv0 = 1.0f / l0_;
    float inv1 = 1.0f / l1_;
    int r0 = m0 + 16 * warp + g;
    float* ob0 = out + ((size_t)b * LQ + r0) * DIM;
    float* ob1 = ob0 + 8 * DIM;
#pragma unroll
    for (int j = 0; j < 16; j++) {
        int c = 8 * j + 2 * t4;
        *(float2*)(ob0 + c) = make_float2(o[j][0] * inv0, o[j][1] * inv0);
        *(float2*)(ob1 + c) = make_float2(o[j][2] * inv1, o[j][3] * inv1);
    }
}

extern "C" void kernel_launch(void* const* d_in, const int* in_sizes, int n_in,
                              void* d_out, int out_size) {
    const float* q = (const float*)d_in[0];
    const float* k = (const float*)d_in[1];
    const float* v = (const float*)d_in[2];
    float* out = (float*)d_out;

    prep_kernel<<<(3 * BATCH * 2048) / 8, 256>>>(q, k, v);

    size_t smem_bytes = (size_t)(2 * Q_ELEMS + 4 * KV_ARR) * 2;
    cudaFuncSetAttribute(attn_kernel,
                         cudaFuncAttributeMaxDynamicSharedMemorySize,
                         (int)smem_bytes);
    dim3 grid(LQ / BM, BATCH);
    attn_kernel<<<grid, NTHREADS, smem_bytes>>>(out);
}

// round 10
// speedup vs baseline: 1.6904x; 1.0726x over previous
#include <cuda_runtime.h>
#include <cuda_bf16.h>
#include <cuda_fp16.h>
#include <math.h>
#include <stdint.h>

#define BATCH 8
#define LQ    2048
#define SK    2048
#define DIM   128
#define BM    128
#define BN    64
#define NTHREADS 256
#define QSTRB 136            // elems per smem row (DIM + 8 pad), 2B each

// pre-split scratch: Q/K bf16 hi/lo (~2^-18), V fp16 hi/lo (~2^-24)
__device__ __nv_bfloat16 g_qh[BATCH * LQ * DIM];
__device__ __nv_bfloat16 g_ql[BATCH * LQ * DIM];
__device__ __nv_bfloat16 g_kh[BATCH * SK * DIM];
__device__ __nv_bfloat16 g_kl[BATCH * SK * DIM];
__device__ __half        g_vh[BATCH * SK * DIM];
__device__ __half        g_vl[BATCH * SK * DIM];

__device__ __forceinline__ uint32_t pack2(__nv_bfloat16 a, __nv_bfloat16 b) {
    __nv_bfloat162 t; t.x = a; t.y = b;
    return *(uint32_t*)&t;
}
__device__ __forceinline__ uint32_t pack2h(__half a, __half b) {
    __half2 t; t.x = a; t.y = b;
    return *(uint32_t*)&t;
}

__global__ void prep_kernel(const float* __restrict__ q,
                            const float* __restrict__ k,
                            const float* __restrict__ v) {
    int row = blockIdx.x * 8 + (threadIdx.x >> 5);
    int lane = threadIdx.x & 31;
    int kind = row / (BATCH * 2048);                  // 0=Q 1=K 2=V
    int r = row - kind * BATCH * 2048;

    const float* src = (kind == 0 ? q : kind == 1 ? k : v) + (size_t)r * DIM;
    float4 val = ((const float4*)src)[lane];
    if (kind < 2) {
        float ss = val.x * val.x + val.y * val.y + val.z * val.z + val.w * val.w;
#pragma unroll
        for (int off = 16; off > 0; off >>= 1)
            ss += __shfl_xor_sync(0xffffffffu, ss, off);
        float inv = (kind == 0 ? 64.0f : 1.0f) / fmaxf(sqrtf(ss), 1e-12f);
        val.x *= inv; val.y *= inv; val.z *= inv; val.w *= inv;
    }
    float f[4] = {val.x, val.y, val.z, val.w};

    if (kind < 2) {
        __nv_bfloat16* dh = (kind == 0 ? g_qh : g_kh) + (size_t)r * DIM;
        __nv_bfloat16* dl = (kind == 0 ? g_ql : g_kl) + (size_t)r * DIM;
        __nv_bfloat16 h[4]; float rres[4];
#pragma unroll
        for (int i = 0; i < 4; i++) {
            h[i] = __float2bfloat16_rn(f[i]);
            rres[i] = f[i] - __bfloat162float(h[i]);
        }
        uint2 hv, lv;
        hv.x = pack2(h[0], h[1]);
        hv.y = pack2(h[2], h[3]);
        lv.x = pack2(__float2bfloat16_rn(rres[0]), __float2bfloat16_rn(rres[1]));
        lv.y = pack2(__float2bfloat16_rn(rres[2]), __float2bfloat16_rn(rres[3]));
        *(uint2*)(dh + lane * 4) = hv;
        *(uint2*)(dl + lane * 4) = lv;
    } else {
        __half* dh = g_vh + (size_t)r * DIM;
        __half* dl = g_vl + (size_t)r * DIM;
        __half h[4]; float rres[4];
#pragma unroll
        for (int i = 0; i < 4; i++) {
            h[i] = __float2half_rn(f[i]);
            rres[i] = f[i] - __half2float(h[i]);
        }
        uint2 hv, lv;
        hv.x = pack2h(h[0], h[1]);
        hv.y = pack2h(h[2], h[3]);
        lv.x = pack2h(__float2half_rn(rres[0]), __float2half_rn(rres[1]));
        lv.y = pack2h(__float2half_rn(rres[2]), __float2half_rn(rres[3]));
        *(uint2*)(dh + lane * 4) = hv;
        *(uint2*)(dl + lane * 4) = lv;
    }
}

__device__ __forceinline__ uint32_t smem_u32(const void* p) {
    return (uint32_t)__cvta_generic_to_shared(p);
}
__device__ __forceinline__ void cp16(uint32_t daddr, const void* g) {
    asm volatile("cp.async.cg.shared.global [%0], [%1], 16;" :: "r"(daddr), "l"(g));
}
__device__ __forceinline__ void cp_commit() {
    asm volatile("cp.async.commit_group;" ::: "memory");
}
__device__ __forceinline__ void cp_wait0() {
    asm volatile("cp.async.wait_group 0;" ::: "memory");
}
__device__ __forceinline__ void ldsm_x4(uint32_t& r0, uint32_t& r1,
                                        uint32_t& r2, uint32_t& r3, uint32_t a) {
    asm volatile("ldmatrix.sync.aligned.m8n8.x4.shared.b16 {%0,%1,%2,%3}, [%4];"
                 : "=r"(r0), "=r"(r1), "=r"(r2), "=r"(r3) : "r"(a));
}
__device__ __forceinline__ void ldsm_x4t(uint32_t& r0, uint32_t& r1,
                                         uint32_t& r2, uint32_t& r3, uint32_t a) {
    asm volatile("ldmatrix.sync.aligned.m8n8.x4.trans.shared.b16 {%0,%1,%2,%3}, [%4];"
                 : "=r"(r0), "=r"(r1), "=r"(r2), "=r"(r3) : "r"(a));
}
__device__ __forceinline__ void mma_bf16(float* c, uint32_t a0, uint32_t a1,
                                         uint32_t a2, uint32_t a3,
                                         uint32_t b0, uint32_t b1) {
    asm volatile(
        "mma.sync.aligned.m16n8k16.row.col.f32.bf16.bf16.f32 "
        "{%0,%1,%2,%3}, {%4,%5,%6,%7}, {%8,%9}, {%0,%1,%2,%3};"
        : "+f"(c[0]), "+f"(c[1]), "+f"(c[2]), "+f"(c[3])
        : "r"(a0), "r"(a1), "r"(a2), "r"(a3), "r"(b0), "r"(b1));
}
__device__ __forceinline__ void mma_f16(float* c, uint32_t a0, uint32_t a1,
                                        uint32_t a2, uint32_t a3,
                                        uint32_t b0, uint32_t b1) {
    asm volatile(
        "mma.sync.aligned.m16n8k16.row.col.f32.f16.f16.f32 "
        "{%0,%1,%2,%3}, {%4,%5,%6,%7}, {%8,%9}, {%0,%1,%2,%3};"
        : "+f"(c[0]), "+f"(c[1]), "+f"(c[2]), "+f"(c[3])
        : "r"(a0), "r"(a1), "r"(a2), "r"(a3), "r"(b0), "r"(b1));
}
__device__ __forceinline__ uint32_t packh2(float x, float y) {
    __half2 t = __float22half2_rn(make_float2(x, y));
    return *(uint32_t*)&t;
}

// smem element-offsets (2-byte units)
#define Q_ELEMS   (BM * QSTRB)          // 17408
#define KV_ARR    (BN * QSTRB)          // 8704
#define STAGE_EL  (4 * KV_ARR)          // 34816
#define KV0_EL    (2 * Q_ELEMS)

__global__ __launch_bounds__(NTHREADS, 1)
void attn_kernel(float* __restrict__ out) {
    extern __shared__ __nv_bfloat16 smem[];
    const uint32_t sbase = smem_u32(smem);

    const int b    = blockIdx.y;
    const int m0   = blockIdx.x * BM;
    const int tid  = threadIdx.x;
    const int warp = tid >> 5;
    const int lane = tid & 31;
    const int g    = lane >> 2;
    const int t4   = lane & 3;

    const void* garr[4] = {g_kh, g_kl, g_vh, g_vl};

    // ---- prologue: Q hi/lo + K/V tile 0 (stage 0) ----
    {
        const __nv_bfloat16* gq[2] = {g_qh, g_ql};
#pragma unroll
        for (int it = 0; it < 16; it++) {
            int arr = it >> 3;
            int i = tid + it * NTHREADS;
            int within = i & 2047;
            int row = within >> 4;
            int chunk = within & 15;
            const __nv_bfloat16* gp = gq[arr] +
                ((size_t)(b * LQ + m0 + row)) * DIM + chunk * 8;
            uint32_t el = (uint32_t)(arr * Q_ELEMS + row * QSTRB + chunk * 8);
            cp16(sbase + el * 2, gp);
        }
#pragma unroll
        for (int it = 0; it < 16; it++) {
            int i = tid + it * NTHREADS;
            int arr = i >> 10;
            int within = i & 1023;
            int row = within >> 4;
            int chunk = within & 15;
            const char* gp = (const char*)garr[arr] +
                (((size_t)(b * SK + row)) * DIM + chunk * 8) * 2;
            uint32_t el = (uint32_t)(KV0_EL + arr * KV_ARR + row * QSTRB + chunk * 8);
            cp16(sbase + el * 2, gp);
        }
    }
    cp_commit();

    float o[16][4];
    float sc[8][4];
    float m0_ = -INFINITY, m1_ = -INFINITY, l0_ = 0.0f, l1_ = 0.0f;
#pragma unroll
    for (int j = 0; j < 16; j++)
#pragma unroll
        for (int c = 0; c < 4; c++) o[j][c] = 0.0f;

    const uint32_t qoff = (uint32_t)(16 * warp + (lane & 15)) * (QSTRB * 2) +
                          (uint32_t)(lane >> 4) * 16;
    const uint32_t koff = (uint32_t)((lane >> 4) * 8 + (lane & 7)) * (QSTRB * 2) +
                          (uint32_t)(lane & 8) * 2;
    const uint32_t voff = (uint32_t)((lane & 8) + (lane & 7)) * (QSTRB * 2) +
                          (uint32_t)((lane & 16) >> 1) * 2;
    const uint32_t qh0 = sbase + qoff;
    const uint32_t ql0 = sbase + Q_ELEMS * 2 + qoff;

    cp_wait0();
    __syncthreads();

    int sidx = 0;
    for (int s0 = 0; s0 < SK; s0 += BN, sidx ^= 1) {
        // ---- prefetch next K/V tile into other stage ----
        if (s0 + BN < SK) {
            uint32_t stel = (uint32_t)(KV0_EL + (sidx ^ 1) * STAGE_EL);
#pragma unroll
            for (int it = 0; it < 16; it++) {
                int i = tid + it * NTHREADS;
                int arr = i >> 10;
                int within = i & 1023;
                int row = within >> 4;
                int chunk = within & 15;
                const char* gp = (const char*)garr[arr] +
                    (((size_t)(b * SK + s0 + BN + row)) * DIM + chunk * 8) * 2;
                uint32_t el = stel + (uint32_t)(arr * KV_ARR + row * QSTRB + chunk * 8);
                cp16(sbase + el * 2, gp);
            }
            cp_commit();
        }

        const uint32_t stb = sbase + (uint32_t)(KV0_EL + sidx * STAGE_EL) * 2;
        const uint32_t kh0 = stb + koff;
        const uint32_t kl0 = stb + KV_ARR * 2 + koff;
        const uint32_t vh0 = stb + 2 * KV_ARR * 2 + voff;
        const uint32_t vl0 = stb + 3 * KV_ARR * 2 + voff;

        // ---- S = Qn Kn^T : 3-pass bf16, pass-major (dep distance 8) ----
#pragma unroll
        for (int j = 0; j < 8; j++)
#pragma unroll
            for (int c = 0; c < 4; c++) sc[j][c] = 0.0f;

#pragma unroll
        for (int ks = 0; ks < DIM / 16; ks++) {
            uint32_t dbyte = (uint32_t)(ks * 16) * 2;
            uint32_t ah[4], al[4];
            ldsm_x4(ah[0], ah[1], ah[2], ah[3], qh0 + dbyte);
            ldsm_x4(al[0], al[1], al[2], al[3], ql0 + dbyte);
            uint32_t bh[4][4], bl[4][4];
#pragma unroll
            for (int jp = 0; jp < 4; jp++) {
                uint32_t nbyte = (uint32_t)(16 * jp) * (QSTRB * 2);
                ldsm_x4(bh[jp][0], bh[jp][1], bh[jp][2], bh[jp][3], kh0 + nbyte + dbyte);
                ldsm_x4(bl[jp][0], bl[jp][1], bl[jp][2], bl[jp][3], kl0 + nbyte + dbyte);
            }
            // pass 1: qh*kh
#pragma unroll
            for (int jp = 0; jp < 4; jp++) {
                mma_bf16(sc[2 * jp],     ah[0], ah[1], ah[2], ah[3], bh[jp][0], bh[jp][1]);
                mma_bf16(sc[2 * jp + 1], ah[0], ah[1], ah[2], ah[3], bh[jp][2], bh[jp][3]);
            }
            // pass 2: qh*kl
#pragma unroll
            for (int jp = 0; jp < 4; jp++) {
                mma_bf16(sc[2 * jp],     ah[0], ah[1], ah[2], ah[3], bl[jp][0], bl[jp][1]);
                mma_bf16(sc[2 * jp + 1], ah[0], ah[1], ah[2], ah[3], bl[jp][2], bl[jp][3]);
            }
            // pass 3: ql*kh
#pragma unroll
            for (int jp = 0; jp < 4; jp++) {
                mma_bf16(sc[2 * jp],     al[0], al[1], al[2], al[3], bh[jp][0], bh[jp][1]);
                mma_bf16(sc[2 * jp + 1], al[0], al[1], al[2], al[3], bh[jp][2], bh[jp][3]);
            }
        }

        // ---- online softmax ----
        float rmax0 = -INFINITY, rmax1 = -INFINITY;
#pragma unroll
        for (int j = 0; j < 8; j++) {
            rmax0 = fmaxf(rmax0, fmaxf(sc[j][0], sc[j][1]));
            rmax1 = fmaxf(rmax1, fmaxf(sc[j][2], sc[j][3]));
        }
#pragma unroll
        for (int off = 1; off <= 2; off <<= 1) {
            rmax0 = fmaxf(rmax0, __shfl_xor_sync(0xffffffffu, rmax0, off));
            rmax1 = fmaxf(rmax1, __shfl_xor_sync(0xffffffffu, rmax1, off));
        }
        float mnew0 = fmaxf(m0_, rmax0);
        float mnew1 = fmaxf(m1_, rmax1);
        float rs0 = 0.0f, rs1 = 0.0f;
#pragma unroll
        for (int j = 0; j < 8; j++) {
            sc[j][0] = __expf(sc[j][0] - mnew0);
            sc[j][1] = __expf(sc[j][1] - mnew0);
            sc[j][2] = __expf(sc[j][2] - mnew1);
            sc[j][3] = __expf(sc[j][3] - mnew1);
            rs0 += sc[j][0] + sc[j][1];
            rs1 += sc[j][2] + sc[j][3];
        }
#pragma unroll
        for (int off = 1; off <= 2; off <<= 1) {
            rs0 += __shfl_xor_sync(0xffffffffu, rs0, off);
            rs1 += __shfl_xor_sync(0xffffffffu, rs1, off);
        }
        if (mnew0 > m0_) {
            float corr = __expf(m0_ - mnew0);
            l0_ = l0_ * corr + rs0;
            m0_ = mnew0;
#pragma unroll
            for (int j = 0; j < 16; j++) { o[j][0] *= corr; o[j][1] *= corr; }
        } else l0_ += rs0;
        if (mnew1 > m1_) {
            float corr = __expf(m1_ - mnew1);
            l1_ = l1_ * corr + rs1;
            m1_ = mnew1;
#pragma unroll
            for (int j = 0; j < 16; j++) { o[j][2] *= corr; o[j][3] *= corr; }
        } else l1_ += rs1;

        // ---- P fragments: single fp16 ----
        uint32_t ph[4][4];
#pragma unroll
        for (int kk = 0; kk < 4; kk++) {
            int j0 = 2 * kk, j1 = 2 * kk + 1;
            ph[kk][0] = packh2(sc[j0][0], sc[j0][1]);
            ph[kk][1] = packh2(sc[j0][2], sc[j0][3]);
            ph[kk][2] = packh2(sc[j1][0], sc[j1][1]);
            ph[kk][3] = packh2(sc[j1][2], sc[j1][3]);
        }

        // ---- O += P V : fp16 2-pass, dp-pairs (dep distance 4) ----
#pragma unroll
        for (int kk = 0; kk < 4; kk++) {
            uint32_t sbyte = (uint32_t)(16 * kk) * (QSTRB * 2);
#pragma unroll
            for (int dph = 0; dph < 4; dph++) {
                uint32_t db0 = (uint32_t)(32 * dph) * 2;
                uint32_t db1 = db0 + 16 * 2;
                uint32_t h0[4], l0r[4], h1[4], l1r[4];
                ldsm_x4t(h0[0], h0[1], h0[2], h0[3], vh0 + sbyte + db0);
                ldsm_x4t(l0r[0], l0r[1], l0r[2], l0r[3], vl0 + sbyte + db0);
                ldsm_x4t(h1[0], h1[1], h1[2], h1[3], vh0 + sbyte + db1);
                ldsm_x4t(l1r[0], l1r[1], l1r[2], l1r[3], vl0 + sbyte + db1);
                float* o0 = o[4 * dph + 0];
                float* o1 = o[4 * dph + 1];
                float* o2 = o[4 * dph + 2];
                float* o3 = o[4 * dph + 3];
                mma_f16(o0, ph[kk][0], ph[kk][1], ph[kk][2], ph[kk][3], h0[0], h0[1]);
                mma_f16(o1, ph[kk][0], ph[kk][1], ph[kk][2], ph[kk][3], h0[2], h0[3]);
                mma_f16(o2, ph[kk][0], ph[kk][1], ph[kk][2], ph[kk][3], h1[0], h1[1]);
                mma_f16(o3, ph[kk][0], ph[kk][1], ph[kk][2], ph[kk][3], h1[2], h1[3]);
                mma_f16(o0, ph[kk][0], ph[kk][1], ph[kk][2], ph[kk][3], l0r[0], l0r[1]);
                mma_f16(o1, ph[kk][0], ph[kk][1], ph[kk][2], ph[kk][3], l0r[2], l0r[3]);
                mma_f16(o2, ph[kk][0], ph[kk][1], ph[kk][2], ph[kk][3], l1r[0], l1r[1]);
                mma_f16(o3, ph[kk][0], ph[kk][1], ph[kk][2], ph[kk][3], l1r[2], l1r[3]);
            }
        }

        cp_wait0();
        __syncthreads();
    }

    // ---- epilogue ----
    float inv0 = 1.0f / l0_;
    float inv1 = 1.0f / l1_;
    int r0 = m0 + 16 * warp + g;
    float* ob0 = out + ((size_t)b * LQ + r0) * DIM;
    float* ob1 = ob0 + 8 * DIM;
#pragma unroll
    for (int j = 0; j < 16; j++) {
        int c = 8 * j + 2 * t4;
        *(float2*)(ob0 + c) = make_float2(o[j][0] * inv0, o[j][1] * inv0);
        *(float2*)(ob1 + c) = make_float2(o[j][2] * inv1, o[j][3] * inv1);
    }
}

extern "C" void kernel_launch(void* const* d_in, const int* in_sizes, int n_in,
                              void* d_out, int out_size) {
    const float* q = (const float*)d_in[0];
    const float* k = (const float*)d_in[1];
    const float* v = (const float*)d_in[2];
    float* out = (float*)d_out;

    prep_kernel<<<(3 * BATCH * 2048) / 8, 256>>>(q, k, v);

    size_t smem_bytes = (size_t)(KV0_EL + 2 * STAGE_EL) * 2;
    cudaFuncSetAttribute(attn_kernel,
                         cudaFuncAttributeMaxDynamicSharedMemorySize,
                         (int)smem_bytes);
    dim3 grid(LQ / BM, BATCH);
    attn_kernel<<<grid, NTHREADS, smem_bytes>>>(out);
}

// round 12
// speedup vs baseline: 2.0436x; 1.2090x over previous
#include <cuda_runtime.h>
#include <cuda_bf16.h>
#include <cuda_fp16.h>
#include <math.h>
#include <stdint.h>

#define BATCH 8
#define LQ    2048
#define SK    2048
#define DIM   128
#define BM    128
#define BN    64
#define NTHREADS 256
#define QSTRB 136            // elems per smem row (DIM + 8 pad), 2B each

// Q/K bf16 hi/lo (~2^-18); V single fp16 (~2^-11, averaged out by softmax)
__device__ __nv_bfloat16 g_qh[BATCH * LQ * DIM];
__device__ __nv_bfloat16 g_ql[BATCH * LQ * DIM];
__device__ __nv_bfloat16 g_kh[BATCH * SK * DIM];
__device__ __nv_bfloat16 g_kl[BATCH * SK * DIM];
__device__ __half        g_vh[BATCH * SK * DIM];

__device__ __forceinline__ float ex2(float x) {
    float r;
    asm("ex2.approx.f32 %0, %1;" : "=f"(r) : "f"(x));
    return r;
}
__device__ __forceinline__ uint32_t pack2(__nv_bfloat16 a, __nv_bfloat16 b) {
    __nv_bfloat162 t; t.x = a; t.y = b;
    return *(uint32_t*)&t;
}
__device__ __forceinline__ uint32_t pack2h(__half a, __half b) {
    __half2 t; t.x = a; t.y = b;
    return *(uint32_t*)&t;
}

// Q scale folds softmax temperature AND log2(e) so kernel uses exp2 directly.
#define QSCALE 92.33248261689366f   // 64 * log2(e)

__global__ void prep_kernel(const float* __restrict__ q,
                            const float* __restrict__ k,
                            const float* __restrict__ v) {
    int row = blockIdx.x * 8 + (threadIdx.x >> 5);
    int lane = threadIdx.x & 31;
    int kind = row / (BATCH * 2048);                  // 0=Q 1=K 2=V
    int r = row - kind * BATCH * 2048;

    const float* src = (kind == 0 ? q : kind == 1 ? k : v) + (size_t)r * DIM;
    float4 val = ((const float4*)src)[lane];
    if (kind < 2) {
        float ss = val.x * val.x + val.y * val.y + val.z * val.z + val.w * val.w;
#pragma unroll
        for (int off = 16; off > 0; off >>= 1)
            ss += __shfl_xor_sync(0xffffffffu, ss, off);
        float inv = (kind == 0 ? QSCALE : 1.0f) / fmaxf(sqrtf(ss), 1e-12f);
        val.x *= inv; val.y *= inv; val.z *= inv; val.w *= inv;
    }
    float f[4] = {val.x, val.y, val.z, val.w};

    if (kind < 2) {
        __nv_bfloat16* dh = (kind == 0 ? g_qh : g_kh) + (size_t)r * DIM;
        __nv_bfloat16* dl = (kind == 0 ? g_ql : g_kl) + (size_t)r * DIM;
        __nv_bfloat16 h[4]; float rres[4];
#pragma unroll
        for (int i = 0; i < 4; i++) {
            h[i] = __float2bfloat16_rn(f[i]);
            rres[i] = f[i] - __bfloat162float(h[i]);
        }
        uint2 hv, lv;
        hv.x = pack2(h[0], h[1]);
        hv.y = pack2(h[2], h[3]);
        lv.x = pack2(__float2bfloat16_rn(rres[0]), __float2bfloat16_rn(rres[1]));
        lv.y = pack2(__float2bfloat16_rn(rres[2]), __float2bfloat16_rn(rres[3]));
        *(uint2*)(dh + lane * 4) = hv;
        *(uint2*)(dl + lane * 4) = lv;
    } else {
        __half* dh = g_vh + (size_t)r * DIM;
        uint2 hv;
        hv.x = pack2h(__float2half_rn(f[0]), __float2half_rn(f[1]));
        hv.y = pack2h(__float2half_rn(f[2]), __float2half_rn(f[3]));
        *(uint2*)(dh + lane * 4) = hv;
    }
}

__device__ __forceinline__ uint32_t smem_u32(const void* p) {
    return (uint32_t)__cvta_generic_to_shared(p);
}
__device__ __forceinline__ void cp16(uint32_t daddr, const void* g) {
    asm volatile("cp.async.cg.shared.global [%0], [%1], 16;" :: "r"(daddr), "l"(g));
}
__device__ __forceinline__ void cp_commit() {
    asm volatile("cp.async.commit_group;" ::: "memory");
}
__device__ __forceinline__ void cp_wait0() {
    asm volatile("cp.async.wait_group 0;" ::: "memory");
}
__device__ __forceinline__ void ldsm_x4(uint32_t& r0, uint32_t& r1,
                                        uint32_t& r2, uint32_t& r3, uint32_t a) {
    asm volatile("ldmatrix.sync.aligned.m8n8.x4.shared.b16 {%0,%1,%2,%3}, [%4];"
                 : "=r"(r0), "=r"(r1), "=r"(r2), "=r"(r3) : "r"(a));
}
__device__ __forceinline__ void ldsm_x4t(uint32_t& r0, uint32_t& r1,
                                         uint32_t& r2, uint32_t& r3, uint32_t a) {
    asm volatile("ldmatrix.sync.aligned.m8n8.x4.trans.shared.b16 {%0,%1,%2,%3}, [%4];"
                 : "=r"(r0), "=r"(r1), "=r"(r2), "=r"(r3) : "r"(a));
}
__device__ __forceinline__ void mma_bf16(float* c, uint32_t a0, uint32_t a1,
                                         uint32_t a2, uint32_t a3,
                                         uint32_t b0, uint32_t b1) {
    asm volatile(
        "mma.sync.aligned.m16n8k16.row.col.f32.bf16.bf16.f32 "
        "{%0,%1,%2,%3}, {%4,%5,%6,%7}, {%8,%9}, {%0,%1,%2,%3};"
        : "+f"(c[0]), "+f"(c[1]), "+f"(c[2]), "+f"(c[3])
        : "r"(a0), "r"(a1), "r"(a2), "r"(a3), "r"(b0), "r"(b1));
}
__device__ __forceinline__ void mma_f16(float* c, uint32_t a0, uint32_t a1,
                                        uint32_t a2, uint32_t a3,
                                        uint32_t b0, uint32_t b1) {
    asm volatile(
        "mma.sync.aligned.m16n8k16.row.col.f32.f16.f16.f32 "
        "{%0,%1,%2,%3}, {%4,%5,%6,%7}, {%8,%9}, {%0,%1,%2,%3};"
        : "+f"(c[0]), "+f"(c[1]), "+f"(c[2]), "+f"(c[3])
        : "r"(a0), "r"(a1), "r"(a2), "r"(a3), "r"(b0), "r"(b1));
}
__device__ __forceinline__ uint32_t packh2(float x, float y) {
    __half2 t = __float22half2_rn(make_float2(x, y));
    return *(uint32_t*)&t;
}

// smem element-offsets (2-byte units)
#define Q_ELEMS   (BM * QSTRB)          // 17408
#define KV_ARR    (BN * QSTRB)          // 8704
#define STAGE_EL  (3 * KV_ARR)          // 26112 (Kh, Kl, Vh)
#define KV0_EL    (2 * Q_ELEMS)

__global__ __launch_bounds__(NTHREADS, 1)
void attn_kernel(float* __restrict__ out) {
    extern __shared__ __nv_bfloat16 smem[];
    const uint32_t sbase = smem_u32(smem);

    const int b    = blockIdx.y;
    const int m0   = blockIdx.x * BM;
    const int tid  = threadIdx.x;
    const int warp = tid >> 5;
    const int lane = tid & 31;
    const int g    = lane >> 2;
    const int t4   = lane & 3;

    const void* garr[3] = {g_kh, g_kl, g_vh};

    // ---- prologue: Q hi/lo + K/V tile 0 (stage 0) ----
    {
        const __nv_bfloat16* gq[2] = {g_qh, g_ql};
#pragma unroll
        for (int it = 0; it < 16; it++) {
            int arr = it >> 3;
            int i = tid + it * NTHREADS;
            int within = i & 2047;
            int row = within >> 4;
            int chunk = within & 15;
            const __nv_bfloat16* gp = gq[arr] +
                ((size_t)(b * LQ + m0 + row)) * DIM + chunk * 8;
            uint32_t el = (uint32_t)(arr * Q_ELEMS + row * QSTRB + chunk * 8);
            cp16(sbase + el * 2, gp);
        }
#pragma unroll
        for (int it = 0; it < 12; it++) {
            int i = tid + it * NTHREADS;
            int arr = i >> 10;
            int within = i & 1023;
            int row = within >> 4;
            int chunk = within & 15;
            const char* gp = (const char*)garr[arr] +
                (((size_t)(b * SK + row)) * DIM + chunk * 8) * 2;
            uint32_t el = (uint32_t)(KV0_EL + arr * KV_ARR + row * QSTRB + chunk * 8);
            cp16(sbase + el * 2, gp);
        }
    }
    cp_commit();

    float o[16][4];
    float sc[8][4];
    float m0_ = -INFINITY, m1_ = -INFINITY, l0_ = 0.0f, l1_ = 0.0f;
#pragma unroll
    for (int j = 0; j < 16; j++)
#pragma unroll
        for (int c = 0; c < 4; c++) o[j][c] = 0.0f;

    const uint32_t qoff = (uint32_t)(16 * warp + (lane & 15)) * (QSTRB * 2) +
                          (uint32_t)(lane >> 4) * 16;
    const uint32_t koff = (uint32_t)((lane >> 4) * 8 + (lane & 7)) * (QSTRB * 2) +
                          (uint32_t)(lane & 8) * 2;
    const uint32_t voff = (uint32_t)((lane & 8) + (lane & 7)) * (QSTRB * 2) +
                          (uint32_t)((lane & 16) >> 1) * 2;
    const uint32_t qh0 = sbase + qoff;
    const uint32_t ql0 = sbase + Q_ELEMS * 2 + qoff;

    cp_wait0();
    __syncthreads();

    int sidx = 0;
    for (int s0 = 0; s0 < SK; s0 += BN, sidx ^= 1) {
        // ---- prefetch next K/V tile into other stage ----
        if (s0 + BN < SK) {
            uint32_t stel = (uint32_t)(KV0_EL + (sidx ^ 1) * STAGE_EL);
#pragma unroll
            for (int it = 0; it < 12; it++) {
                int i = tid + it * NTHREADS;
                int arr = i >> 10;
                int within = i & 1023;
                int row = within >> 4;
                int chunk = within & 15;
                const char* gp = (const char*)garr[arr] +
                    (((size_t)(b * SK + s0 + BN + row)) * DIM + chunk * 8) * 2;
                uint32_t el = stel + (uint32_t)(arr * KV_ARR + row * QSTRB + chunk * 8);
                cp16(sbase + el * 2, gp);
            }
            cp_commit();
        }

        const uint32_t stb = sbase + (uint32_t)(KV0_EL + sidx * STAGE_EL) * 2;
        const uint32_t kh0 = stb + koff;
        const uint32_t kl0 = stb + KV_ARR * 2 + koff;
        const uint32_t vh0 = stb + 2 * KV_ARR * 2 + voff;

        // ---- S = Qn Kn^T : 3-pass bf16, pass-major (dep distance 8) ----
#pragma unroll
        for (int j = 0; j < 8; j++)
#pragma unroll
            for (int c = 0; c < 4; c++) sc[j][c] = 0.0f;

#pragma unroll
        for (int ks = 0; ks < DIM / 16; ks++) {
            uint32_t dbyte = (uint32_t)(ks * 16) * 2;
            uint32_t ah[4], al[4];
            ldsm_x4(ah[0], ah[1], ah[2], ah[3], qh0 + dbyte);
            ldsm_x4(al[0], al[1], al[2], al[3], ql0 + dbyte);
            uint32_t bh[4][4], bl[4][4];
#pragma unroll
            for (int jp = 0; jp < 4; jp++) {
                uint32_t nbyte = (uint32_t)(16 * jp) * (QSTRB * 2);
                ldsm_x4(bh[jp][0], bh[jp][1], bh[jp][2], bh[jp][3], kh0 + nbyte + dbyte);
                ldsm_x4(bl[jp][0], bl[jp][1], bl[jp][2], bl[jp][3], kl0 + nbyte + dbyte);
            }
#pragma unroll
            for (int jp = 0; jp < 4; jp++) {
                mma_bf16(sc[2 * jp],     ah[0], ah[1], ah[2], ah[3], bh[jp][0], bh[jp][1]);
                mma_bf16(sc[2 * jp + 1], ah[0], ah[1], ah[2], ah[3], bh[jp][2], bh[jp][3]);
            }
#pragma unroll
            for (int jp = 0; jp < 4; jp++) {
                mma_bf16(sc[2 * jp],     ah[0], ah[1], ah[2], ah[3], bl[jp][0], bl[jp][1]);
                mma_bf16(sc[2 * jp + 1], ah[0], ah[1], ah[2], ah[3], bl[jp][2], bl[jp][3]);
            }
#pragma unroll
            for (int jp = 0; jp < 4; jp++) {
                mma_bf16(sc[2 * jp],     al[0], al[1], al[2], al[3], bh[jp][0], bh[jp][1]);
                mma_bf16(sc[2 * jp + 1], al[0], al[1], al[2], al[3], bh[jp][2], bh[jp][3]);
            }
        }

        // ---- online softmax (log2 units; ex2.approx) ----
        float rmax0 = -INFINITY, rmax1 = -INFINITY;
#pragma unroll
        for (int j = 0; j < 8; j++) {
            rmax0 = fmaxf(rmax0, fmaxf(sc[j][0], sc[j][1]));
            rmax1 = fmaxf(rmax1, fmaxf(sc[j][2], sc[j][3]));
        }
#pragma unroll
        for (int off = 1; off <= 2; off <<= 1) {
            rmax0 = fmaxf(rmax0, __shfl_xor_sync(0xffffffffu, rmax0, off));
            rmax1 = fmaxf(rmax1, __shfl_xor_sync(0xffffffffu, rmax1, off));
        }
        float mnew0 = fmaxf(m0_, rmax0);
        float mnew1 = fmaxf(m1_, rmax1);
        float rs0 = 0.0f, rs1 = 0.0f;
#pragma unroll
        for (int j = 0; j < 8; j++) {
            sc[j][0] = ex2(sc[j][0] - mnew0);
            sc[j][1] = ex2(sc[j][1] - mnew0);
            sc[j][2] = ex2(sc[j][2] - mnew1);
            sc[j][3] = ex2(sc[j][3] - mnew1);
            rs0 += sc[j][0] + sc[j][1];
            rs1 += sc[j][2] + sc[j][3];
        }
#pragma unroll
        for (int off = 1; off <= 2; off <<= 1) {
            rs0 += __shfl_xor_sync(0xffffffffu, rs0, off);
            rs1 += __shfl_xor_sync(0xffffffffu, rs1, off);
        }
        if (mnew0 > m0_) {
            float corr = ex2(m0_ - mnew0);
            l0_ = l0_ * corr + rs0;
            m0_ = mnew0;
#pragma unroll
            for (int j = 0; j < 16; j++) { o[j][0] *= corr; o[j][1] *= corr; }
        } else l0_ += rs0;
        if (mnew1 > m1_) {
            float corr = ex2(m1_ - mnew1);
            l1_ = l1_ * corr + rs1;
            m1_ = mnew1;
#pragma unroll
            for (int j = 0; j < 16; j++) { o[j][2] *= corr; o[j][3] *= corr; }
        } else l1_ += rs1;

        // ---- P fragments: single fp16 ----
        uint32_t ph[4][4];
#pragma unroll
        for (int kk = 0; kk < 4; kk++) {
            int j0 = 2 * kk, j1 = 2 * kk + 1;
            ph[kk][0] = packh2(sc[j0][0], sc[j0][1]);
            ph[kk][1] = packh2(sc[j0][2], sc[j0][3]);
            ph[kk][2] = packh2(sc[j1][0], sc[j1][1]);
            ph[kk][3] = packh2(sc[j1][2], sc[j1][3]);
        }

        // ---- O += P V : single-pass fp16 V ----
#pragma unroll
        for (int kk = 0; kk < 4; kk++) {
            uint32_t sbyte = (uint32_t)(16 * kk) * (QSTRB * 2);
#pragma unroll
            for (int dph = 0; dph < 4; dph++) {
                uint32_t db0 = (uint32_t)(32 * dph) * 2;
                uint32_t db1 = db0 + 16 * 2;
                uint32_t h0[4], h1[4];
                ldsm_x4t(h0[0], h0[1], h0[2], h0[3], vh0 + sbyte + db0);
                ldsm_x4t(h1[0], h1[1], h1[2], h1[3], vh0 + sbyte + db1);
                mma_f16(o[4 * dph + 0], ph[kk][0], ph[kk][1], ph[kk][2], ph[kk][3], h0[0], h0[1]);
                mma_f16(o[4 * dph + 1], ph[kk][0], ph[kk][1], ph[kk][2], ph[kk][3], h0[2], h0[3]);
                mma_f16(o[4 * dph + 2], ph[kk][0], ph[kk][1], ph[kk][2], ph[kk][3], h1[0], h1[1]);
                mma_f16(o[4 * dph + 3], ph[kk][0], ph[kk][1], ph[kk][2], ph[kk][3], h1[2], h1[3]);
            }
        }

        cp_wait0();
        __syncthreads();
    }

    // ---- epilogue ----
    float inv0 = 1.0f / l0_;
    float inv1 = 1.0f / l1_;
    int r0 = m0 + 16 * warp + g;
    float* ob0 = out + ((size_t)b * LQ + r0) * DIM;
    float* ob1 = ob0 + 8 * DIM;
#pragma unroll
    for (int j = 0; j < 16; j++) {
        int c = 8 * j + 2 * t4;
        *(float2*)(ob0 + c) = make_float2(o[j][0] * inv0, o[j][1] * inv0);
        *(float2*)(ob1 + c) = make_float2(o[j][2] * inv1, o[j][3] * inv1);
    }
}

extern "C" void kernel_launch(void* const* d_in, const int* in_sizes, int n_in,
                              void* d_out, int out_size) {
    const float* q = (const float*)d_in[0];
    const float* k = (const float*)d_in[1];
    const float* v = (const float*)d_in[2];
    float* out = (float*)d_out;

    prep_kernel<<<(3 * BATCH * 2048) / 8, 256>>>(q, k, v);

    size_t smem_bytes = (size_t)(KV0_EL + 2 * STAGE_EL) * 2;
    cudaFuncSetAttribute(attn_kernel,
                         cudaFuncAttributeMaxDynamicSharedMemorySize,
                         (int)smem_bytes);
    dim3 grid(LQ / BM, BATCH);
    attn_kernel<<<grid, NTHREADS, smem_bytes>>>(out);
}

// round 14
// speedup vs baseline: 2.1089x; 1.0320x over previous
#include <cuda_runtime.h>
#include <cuda_bf16.h>
#include <cuda_fp16.h>
#include <math.h>
#include <stdint.h>

#define BATCH 8
#define LQ    2048
#define SK    2048
#define DIM   128
#define BM    128
#define BN    64
#define NTHREADS 256
#define NTILES (SK / BN)
#define QSTRB 136            // elems per smem row (DIM + 8 pad), 2B each

// Q/K bf16 hi/lo (~2^-18); V single fp16 (~2^-11, averaged out by softmax)
__device__ __nv_bfloat16 g_qh[BATCH * LQ * DIM];
__device__ __nv_bfloat16 g_ql[BATCH * LQ * DIM];
__device__ __nv_bfloat16 g_kh[BATCH * SK * DIM];
__device__ __nv_bfloat16 g_kl[BATCH * SK * DIM];
__device__ __half        g_vh[BATCH * SK * DIM];

__device__ __forceinline__ float ex2(float x) {
    float r;
    asm("ex2.approx.f32 %0, %1;" : "=f"(r) : "f"(x));
    return r;
}
__device__ __forceinline__ uint32_t pack2(__nv_bfloat16 a, __nv_bfloat16 b) {
    __nv_bfloat162 t; t.x = a; t.y = b;
    return *(uint32_t*)&t;
}
__device__ __forceinline__ uint32_t pack2h(__half a, __half b) {
    __half2 t; t.x = a; t.y = b;
    return *(uint32_t*)&t;
}

#define QSCALE 92.33248261689366f   // 64 * log2(e)

__global__ void prep_kernel(const float* __restrict__ q,
                            const float* __restrict__ k,
                            const float* __restrict__ v) {
    int row = blockIdx.x * 8 + (threadIdx.x >> 5);
    int lane = threadIdx.x & 31;
    int kind = row / (BATCH * 2048);                  // 0=Q 1=K 2=V
    int r = row - kind * BATCH * 2048;

    const float* src = (kind == 0 ? q : kind == 1 ? k : v) + (size_t)r * DIM;
    float4 val = ((const float4*)src)[lane];
    if (kind < 2) {
        float ss = val.x * val.x + val.y * val.y + val.z * val.z + val.w * val.w;
#pragma unroll
        for (int off = 16; off > 0; off >>= 1)
            ss += __shfl_xor_sync(0xffffffffu, ss, off);
        float inv = (kind == 0 ? QSCALE : 1.0f) / fmaxf(sqrtf(ss), 1e-12f);
        val.x *= inv; val.y *= inv; val.z *= inv; val.w *= inv;
    }
    float f[4] = {val.x, val.y, val.z, val.w};

    if (kind < 2) {
        __nv_bfloat16* dh = (kind == 0 ? g_qh : g_kh) + (size_t)r * DIM;
        __nv_bfloat16* dl = (kind == 0 ? g_ql : g_kl) + (size_t)r * DIM;
        __nv_bfloat16 h[4]; float rres[4];
#pragma unroll
        for (int i = 0; i < 4; i++) {
            h[i] = __float2bfloat16_rn(f[i]);
            rres[i] = f[i] - __bfloat162float(h[i]);
        }
        uint2 hv, lv;
        hv.x = pack2(h[0], h[1]);
        hv.y = pack2(h[2], h[3]);
        lv.x = pack2(__float2bfloat16_rn(rres[0]), __float2bfloat16_rn(rres[1]));
        lv.y = pack2(__float2bfloat16_rn(rres[2]), __float2bfloat16_rn(rres[3]));
        *(uint2*)(dh + lane * 4) = hv;
        *(uint2*)(dl + lane * 4) = lv;
    } else {
        __half* dh = g_vh + (size_t)r * DIM;
        uint2 hv;
        hv.x = pack2h(__float2half_rn(f[0]), __float2half_rn(f[1]));
        hv.y = pack2h(__float2half_rn(f[2]), __float2half_rn(f[3]));
        *(uint2*)(dh + lane * 4) = hv;
    }
}

__device__ __forceinline__ uint32_t smem_u32(const void* p) {
    return (uint32_t)__cvta_generic_to_shared(p);
}
__device__ __forceinline__ void cp16(uint32_t daddr, const void* g) {
    asm volatile("cp.async.cg.shared.global [%0], [%1], 16;" :: "r"(daddr), "l"(g));
}
__device__ __forceinline__ void cp_commit() {
    asm volatile("cp.async.commit_group;" ::: "memory");
}
__device__ __forceinline__ void cp_wait0() {
    asm volatile("cp.async.wait_group 0;" ::: "memory");
}
__device__ __forceinline__ void cp_wait1() {
    asm volatile("cp.async.wait_group 1;" ::: "memory");
}
__device__ __forceinline__ void ldsm_x4(uint32_t& r0, uint32_t& r1,
                                        uint32_t& r2, uint32_t& r3, uint32_t a) {
    asm volatile("ldmatrix.sync.aligned.m8n8.x4.shared.b16 {%0,%1,%2,%3}, [%4];"
                 : "=r"(r0), "=r"(r1), "=r"(r2), "=r"(r3) : "r"(a));
}
__device__ __forceinline__ void ldsm_x4t(uint32_t& r0, uint32_t& r1,
                                         uint32_t& r2, uint32_t& r3, uint32_t a) {
    asm volatile("ldmatrix.sync.aligned.m8n8.x4.trans.shared.b16 {%0,%1,%2,%3}, [%4];"
                 : "=r"(r0), "=r"(r1), "=r"(r2), "=r"(r3) : "r"(a));
}
__device__ __forceinline__ void mma_bf16(float* c, uint32_t a0, uint32_t a1,
                                         uint32_t a2, uint32_t a3,
                                         uint32_t b0, uint32_t b1) {
    asm volatile(
        "mma.sync.aligned.m16n8k16.row.col.f32.bf16.bf16.f32 "
        "{%0,%1,%2,%3}, {%4,%5,%6,%7}, {%8,%9}, {%0,%1,%2,%3};"
        : "+f"(c[0]), "+f"(c[1]), "+f"(c[2]), "+f"(c[3])
        : "r"(a0), "r"(a1), "r"(a2), "r"(a3), "r"(b0), "r"(b1));
}
__device__ __forceinline__ void mma_f16(float* c, uint32_t a0, uint32_t a1,
                                        uint32_t a2, uint32_t a3,
                                        uint32_t b0, uint32_t b1) {
    asm volatile(
        "mma.sync.aligned.m16n8k16.row.col.f32.f16.f16.f32 "
        "{%0,%1,%2,%3}, {%4,%5,%6,%7}, {%8,%9}, {%0,%1,%2,%3};"
        : "+f"(c[0]), "+f"(c[1]), "+f"(c[2]), "+f"(c[3])
        : "r"(a0), "r"(a1), "r"(a2), "r"(a3), "r"(b0), "r"(b1));
}
__device__ __forceinline__ uint32_t packh2(float x, float y) {
    __half2 t = __float22half2_rn(make_float2(x, y));
    return *(uint32_t*)&t;
}

// smem element-offsets (2-byte units)
#define Q_ELEMS   (BM * QSTRB)          // 17408
#define KV_ARR    (BN * QSTRB)          // 8704
#define STAGE_EL  (3 * KV_ARR)          // 26112 (Kh, Kl, Vh)
#define KV0_EL    (2 * Q_ELEMS)
// total smem = (KV0_EL + 3*STAGE_EL)*2 = 226304 bytes

// ---- QK^T for one tile into sc (3-pass bf16, pass-major) ----
__device__ __forceinline__ void qk_issue(float (&sc)[8][4],
                                         uint32_t qh0, uint32_t ql0,
                                         uint32_t kh0, uint32_t kl0) {
#pragma unroll
    for (int j = 0; j < 8; j++)
#pragma unroll
        for (int c = 0; c < 4; c++) sc[j][c] = 0.0f;
#pragma unroll
    for (int ks = 0; ks < DIM / 16; ks++) {
        uint32_t dbyte = (uint32_t)(ks * 16) * 2;
        uint32_t ah[4], al[4];
        ldsm_x4(ah[0], ah[1], ah[2], ah[3], qh0 + dbyte);
        ldsm_x4(al[0], al[1], al[2], al[3], ql0 + dbyte);
        uint32_t bh[4][4], bl[4][4];
#pragma unroll
        for (int jp = 0; jp < 4; jp++) {
            uint32_t nbyte = (uint32_t)(16 * jp) * (QSTRB * 2);
            ldsm_x4(bh[jp][0], bh[jp][1], bh[jp][2], bh[jp][3], kh0 + nbyte + dbyte);
            ldsm_x4(bl[jp][0], bl[jp][1], bl[jp][2], bl[jp][3], kl0 + nbyte + dbyte);
        }
#pragma unroll
        for (int jp = 0; jp < 4; jp++) {
            mma_bf16(sc[2 * jp],     ah[0], ah[1], ah[2], ah[3], bh[jp][0], bh[jp][1]);
            mma_bf16(sc[2 * jp + 1], ah[0], ah[1], ah[2], ah[3], bh[jp][2], bh[jp][3]);
        }
#pragma unroll
        for (int jp = 0; jp < 4; jp++) {
            mma_bf16(sc[2 * jp],     ah[0], ah[1], ah[2], ah[3], bl[jp][0], bl[jp][1]);
            mma_bf16(sc[2 * jp + 1], ah[0], ah[1], ah[2], ah[3], bl[jp][2], bl[jp][3]);
        }
#pragma unroll
        for (int jp = 0; jp < 4; jp++) {
            mma_bf16(sc[2 * jp],     al[0], al[1], al[2], al[3], bh[jp][0], bh[jp][1]);
            mma_bf16(sc[2 * jp + 1], al[0], al[1], al[2], al[3], bh[jp][2], bh[jp][3]);
        }
    }
}

// ---- softmax + PV for one tile (consumes sc, updates o/m/l) ----
__device__ __forceinline__ void softmax_pv(float (&sc)[8][4], float (&o)[16][4],
                                           float& m0_, float& m1_,
                                           float& l0_, float& l1_,
                                           uint32_t vh0) {
    float rmax0 = -INFINITY, rmax1 = -INFINITY;
#pragma unroll
    for (int j = 0; j < 8; j++) {
        rmax0 = fmaxf(rmax0, fmaxf(sc[j][0], sc[j][1]));
        rmax1 = fmaxf(rmax1, fmaxf(sc[j][2], sc[j][3]));
    }
#pragma unroll
    for (int off = 1; off <= 2; off <<= 1) {
        rmax0 = fmaxf(rmax0, __shfl_xor_sync(0xffffffffu, rmax0, off));
        rmax1 = fmaxf(rmax1, __shfl_xor_sync(0xffffffffu, rmax1, off));
    }
    float mnew0 = fmaxf(m0_, rmax0);
    float mnew1 = fmaxf(m1_, rmax1);
    float rs0 = 0.0f, rs1 = 0.0f;
#pragma unroll
    for (int j = 0; j < 8; j++) {
        sc[j][0] = ex2(sc[j][0] - mnew0);
        sc[j][1] = ex2(sc[j][1] - mnew0);
        sc[j][2] = ex2(sc[j][2] - mnew1);
        sc[j][3] = ex2(sc[j][3] - mnew1);
        rs0 += sc[j][0] + sc[j][1];
        rs1 += sc[j][2] + sc[j][3];
    }
#pragma unroll
    for (int off = 1; off <= 2; off <<= 1) {
        rs0 += __shfl_xor_sync(0xffffffffu, rs0, off);
        rs1 += __shfl_xor_sync(0xffffffffu, rs1, off);
    }
    if (mnew0 > m0_) {
        float corr = ex2(m0_ - mnew0);
        l0_ = l0_ * corr + rs0;
        m0_ = mnew0;
#pragma unroll
        for (int j = 0; j < 16; j++) { o[j][0] *= corr; o[j][1] *= corr; }
    } else l0_ += rs0;
    if (mnew1 > m1_) {
        float corr = ex2(m1_ - mnew1);
        l1_ = l1_ * corr + rs1;
        m1_ = mnew1;
#pragma unroll
        for (int j = 0; j < 16; j++) { o[j][2] *= corr; o[j][3] *= corr; }
    } else l1_ += rs1;

    uint32_t ph[4][4];
#pragma unroll
    for (int kk = 0; kk < 4; kk++) {
        int j0 = 2 * kk, j1 = 2 * kk + 1;
        ph[kk][0] = packh2(sc[j0][0], sc[j0][1]);
        ph[kk][1] = packh2(sc[j0][2], sc[j0][3]);
        ph[kk][2] = packh2(sc[j1][0], sc[j1][1]);
        ph[kk][3] = packh2(sc[j1][2], sc[j1][3]);
    }
#pragma unroll
    for (int kk = 0; kk < 4; kk++) {
        uint32_t sbyte = (uint32_t)(16 * kk) * (QSTRB * 2);
#pragma unroll
        for (int dph = 0; dph < 4; dph++) {
            uint32_t db0 = (uint32_t)(32 * dph) * 2;
            uint32_t db1 = db0 + 16 * 2;
            uint32_t h0[4], h1[4];
            ldsm_x4t(h0[0], h0[1], h0[2], h0[3], vh0 + sbyte + db0);
            ldsm_x4t(h1[0], h1[1], h1[2], h1[3], vh0 + sbyte + db1);
            mma_f16(o[4 * dph + 0], ph[kk][0], ph[kk][1], ph[kk][2], ph[kk][3], h0[0], h0[1]);
            mma_f16(o[4 * dph + 1], ph[kk][0], ph[kk][1], ph[kk][2], ph[kk][3], h0[2], h0[3]);
            mma_f16(o[4 * dph + 2], ph[kk][0], ph[kk][1], ph[kk][2], ph[kk][3], h1[0], h1[1]);
            mma_f16(o[4 * dph + 3], ph[kk][0], ph[kk][1], ph[kk][2], ph[kk][3], h1[2], h1[3]);
        }
    }
}

__global__ __launch_bounds__(NTHREADS, 1)
void attn_kernel(float* __restrict__ out) {
    extern __shared__ __nv_bfloat16 smem[];
    const uint32_t sbase = smem_u32(smem);

    const int b    = blockIdx.y;
    const int m0   = blockIdx.x * BM;
    const int tid  = threadIdx.x;
    const int warp = tid >> 5;
    const int lane = tid & 31;
    const int g    = lane >> 2;
    const int t4   = lane & 3;

    const void* garr[3] = {g_kh, g_kl, g_vh};

    // load K/V tile t into stage t%3
    auto load_kv = [&](int t) {
        uint32_t stel = (uint32_t)(KV0_EL + (t % 3) * STAGE_EL);
#pragma unroll
        for (int it = 0; it < 12; it++) {
            int i = tid + it * NTHREADS;
            int arr = i >> 10;
            int within = i & 1023;
            int row = within >> 4;
            int chunk = within & 15;
            const char* gp = (const char*)garr[arr] +
                (((size_t)(b * SK + t * BN + row)) * DIM + chunk * 8) * 2;
            uint32_t el = stel + (uint32_t)(arr * KV_ARR + row * QSTRB + chunk * 8);
            cp16(sbase + el * 2, gp);
        }
    };

    // ---- prologue: Q hi/lo + KV(0); then KV(1) ----
    {
        const __nv_bfloat16* gq[2] = {g_qh, g_ql};
#pragma unroll
        for (int it = 0; it < 16; it++) {
            int arr = it >> 3;
            int i = tid + it * NTHREADS;
            int within = i & 2047;
            int row = within >> 4;
            int chunk = within & 15;
            const __nv_bfloat16* gp = gq[arr] +
                ((size_t)(b * LQ + m0 + row)) * DIM + chunk * 8;
            uint32_t el = (uint32_t)(arr * Q_ELEMS + row * QSTRB + chunk * 8);
            cp16(sbase + el * 2, gp);
        }
        load_kv(0);
        cp_commit();
        load_kv(1);
        cp_commit();
    }

    float o[16][4];
    float scA[8][4], scB[8][4];
    float m0_ = -INFINITY, m1_ = -INFINITY, l0_ = 0.0f, l1_ = 0.0f;
#pragma unroll
    for (int j = 0; j < 16; j++)
#pragma unroll
        for (int c = 0; c < 4; c++) o[j][c] = 0.0f;

    const uint32_t qoff = (uint32_t)(16 * warp + (lane & 15)) * (QSTRB * 2) +
                          (uint32_t)(lane >> 4) * 16;
    const uint32_t koff = (uint32_t)((lane >> 4) * 8 + (lane & 7)) * (QSTRB * 2) +
                          (uint32_t)(lane & 8) * 2;
    const uint32_t voff = (uint32_t)((lane & 8) + (lane & 7)) * (QSTRB * 2) +
                          (uint32_t)((lane & 16) >> 1) * 2;
    const uint32_t qh0 = sbase + qoff;
    const uint32_t ql0 = sbase + Q_ELEMS * 2 + qoff;

    auto kh_of = [&](int t) {
        return sbase + (uint32_t)(KV0_EL + (t % 3) * STAGE_EL) * 2 + koff;
    };
    auto kl_of = [&](int t) {
        return sbase + (uint32_t)(KV0_EL + (t % 3) * STAGE_EL + KV_ARR) * 2 + koff;
    };
    auto vh_of = [&](int t) {
        return sbase + (uint32_t)(KV0_EL + (t % 3) * STAGE_EL + 2 * KV_ARR) * 2 + voff;
    };

    cp_wait1();          // Q + KV(0) resident
    __syncthreads();
    qk_issue(scA, qh0, ql0, kh_of(0), kl_of(0));

    for (int i = 0; i < NTILES; i += 2) {
        // ---- even tile i: QK(i+1) overlaps softmax(i) ----
        cp_wait0();                  // KV(i+1) resident
        __syncthreads();
        qk_issue(scB, qh0, ql0, kh_of(i + 1), kl_of(i + 1));
        if (i + 2 < NTILES) { load_kv(i + 2); cp_commit(); }
        softmax_pv(scA, o, m0_, m1_, l0_, l1_, vh_of(i));

        // ---- odd tile i+1: QK(i+2) overlaps softmax(i+1) ----
        cp_wait0();                  // KV(i+2) resident (if any)
        __syncthreads();
        if (i + 2 < NTILES) qk_issue(scA, qh0, ql0, kh_of(i + 2), kl_of(i + 2));
        if (i + 3 < NTILES) { load_kv(i + 3); cp_commit(); }
        softmax_pv(scB, o, m0_, m1_, l0_, l1_, vh_of(i + 1));
    }

    // ---- epilogue ----
    float inv0 = 1.0f / l0_;
    float inv1 = 1.0f / l1_;
    int r0 = m0 + 16 * warp + g;
    float* ob0 = out + ((size_t)b * LQ + r0) * DIM;
    float* ob1 = ob0 + 8 * DIM;
#pragma unroll
    for (int j = 0; j < 16; j++) {
        int c = 8 * j + 2 * t4;
        *(float2*)(ob0 + c) = make_float2(o[j][0] * inv0, o[j][1] * inv0);
        *(float2*)(ob1 + c) = make_float2(o[j][2] * inv1, o[j][3] * inv1);
    }
}

extern "C" void kernel_launch(void* const* d_in, const int* in_sizes, int n_in,
                              void* d_out, int out_size) {
    const float* q = (const float*)d_in[0];
    const float* k = (const float*)d_in[1];
    const float* v = (const float*)d_in[2];
    float* out = (float*)d_out;

    prep_kernel<<<(3 * BATCH * 2048) / 8, 256>>>(q, k, v);

    size_t smem_bytes = (size_t)(KV0_EL + 3 * STAGE_EL) * 2;
    cudaFuncSetAttribute(attn_kernel,
                         cudaFuncAttributeMaxDynamicSharedMemorySize,
                         (int)smem_bytes);
    dim3 grid(LQ / BM, BATCH);
    attn_kernel<<<grid, NTHREADS, smem_bytes>>>(out);
}

// round 15
// speedup vs baseline: 2.2220x; 1.0536x over previous
#include <cuda_runtime.h>
#include <cuda_bf16.h>
#include <cuda_fp16.h>
#include <math.h>
#include <stdint.h>

#define BATCH 8
#define LQ    2048
#define SK    2048
#define DIM   128
#define BM    128
#define BN    64
#define NTHREADS 256
#define NTILES (SK / BN)
#define QSTRB 136            // elems per smem row (DIM + 8 pad), 2B each

// Q/K bf16 hi/lo (~2^-18); V single fp16 (~2^-11, averaged out by softmax)
__device__ __nv_bfloat16 g_qh[BATCH * LQ * DIM];
__device__ __nv_bfloat16 g_ql[BATCH * LQ * DIM];
__device__ __nv_bfloat16 g_kh[BATCH * SK * DIM];
__device__ __nv_bfloat16 g_kl[BATCH * SK * DIM];
__device__ __half        g_vh[BATCH * SK * DIM];

__device__ __forceinline__ float ex2(float x) {
    float r;
    asm("ex2.approx.f32 %0, %1;" : "=f"(r) : "f"(x));
    return r;
}
__device__ __forceinline__ uint32_t hex2(uint32_t h2) {
    uint32_t r;
    asm("ex2.approx.f16x2 %0, %1;" : "=r"(r) : "r"(h2));
    return r;
}
__device__ __forceinline__ uint32_t pack2(__nv_bfloat16 a, __nv_bfloat16 b) {
    __nv_bfloat162 t; t.x = a; t.y = b;
    return *(uint32_t*)&t;
}
__device__ __forceinline__ uint32_t pack2h(__half a, __half b) {
    __half2 t; t.x = a; t.y = b;
    return *(uint32_t*)&t;
}
__device__ __forceinline__ uint32_t packh2(float x, float y) {
    __half2 t = __float22half2_rn(make_float2(x, y));
    return *(uint32_t*)&t;
}

#define QSCALE 92.33248261689366f   // 64 * log2(e)

__global__ void prep_kernel(const float* __restrict__ q,
                            const float* __restrict__ k,
                            const float* __restrict__ v) {
    int row = blockIdx.x * 8 + (threadIdx.x >> 5);
    int lane = threadIdx.x & 31;
    int kind = row / (BATCH * 2048);                  // 0=Q 1=K 2=V
    int r = row - kind * BATCH * 2048;

    const float* src = (kind == 0 ? q : kind == 1 ? k : v) + (size_t)r * DIM;
    float4 val = ((const float4*)src)[lane];
    if (kind < 2) {
        float ss = val.x * val.x + val.y * val.y + val.z * val.z + val.w * val.w;
#pragma unroll
        for (int off = 16; off > 0; off >>= 1)
            ss += __shfl_xor_sync(0xffffffffu, ss, off);
        float inv = (kind == 0 ? QSCALE : 1.0f) / fmaxf(sqrtf(ss), 1e-12f);
        val.x *= inv; val.y *= inv; val.z *= inv; val.w *= inv;
    }
    float f[4] = {val.x, val.y, val.z, val.w};

    if (kind < 2) {
        __nv_bfloat16* dh = (kind == 0 ? g_qh : g_kh) + (size_t)r * DIM;
        __nv_bfloat16* dl = (kind == 0 ? g_ql : g_kl) + (size_t)r * DIM;
        __nv_bfloat16 h[4]; float rres[4];
#pragma unroll
        for (int i = 0; i < 4; i++) {
            h[i] = __float2bfloat16_rn(f[i]);
            rres[i] = f[i] - __bfloat162float(h[i]);
        }
        uint2 hv, lv;
        hv.x = pack2(h[0], h[1]);
        hv.y = pack2(h[2], h[3]);
        lv.x = pack2(__float2bfloat16_rn(rres[0]), __float2bfloat16_rn(rres[1]));
        lv.y = pack2(__float2bfloat16_rn(rres[2]), __float2bfloat16_rn(rres[3]));
        *(uint2*)(dh + lane * 4) = hv;
        *(uint2*)(dl + lane * 4) = lv;
    } else {
        __half* dh = g_vh + (size_t)r * DIM;
        uint2 hv;
        hv.x = pack2h(__float2half_rn(f[0]), __float2half_rn(f[1]));
        hv.y = pack2h(__float2half_rn(f[2]), __float2half_rn(f[3]));
        *(uint2*)(dh + lane * 4) = hv;
    }
}

__device__ __forceinline__ uint32_t smem_u32(const void* p) {
    return (uint32_t)__cvta_generic_to_shared(p);
}
__device__ __forceinline__ void cp16(uint32_t daddr, const void* g) {
    asm volatile("cp.async.cg.shared.global [%0], [%1], 16;" :: "r"(daddr), "l"(g));
}
__device__ __forceinline__ void cp_commit() {
    asm volatile("cp.async.commit_group;" ::: "memory");
}
__device__ __forceinline__ void cp_wait0() {
    asm volatile("cp.async.wait_group 0;" ::: "memory");
}
__device__ __forceinline__ void cp_wait1() {
    asm volatile("cp.async.wait_group 1;" ::: "memory");
}
__device__ __forceinline__ void ldsm_x4(uint32_t& r0, uint32_t& r1,
                                        uint32_t& r2, uint32_t& r3, uint32_t a) {
    asm volatile("ldmatrix.sync.aligned.m8n8.x4.shared.b16 {%0,%1,%2,%3}, [%4];"
                 : "=r"(r0), "=r"(r1), "=r"(r2), "=r"(r3) : "r"(a));
}
__device__ __forceinline__ void ldsm_x4t(uint32_t& r0, uint32_t& r1,
                                         uint32_t& r2, uint32_t& r3, uint32_t a) {
    asm volatile("ldmatrix.sync.aligned.m8n8.x4.trans.shared.b16 {%0,%1,%2,%3}, [%4];"
                 : "=r"(r0), "=r"(r1), "=r"(r2), "=r"(r3) : "r"(a));
}
__device__ __forceinline__ void ldsm_x2t(uint32_t& r0, uint32_t& r1, uint32_t a) {
    asm volatile("ldmatrix.sync.aligned.m8n8.x2.trans.shared.b16 {%0,%1}, [%2];"
                 : "=r"(r0), "=r"(r1) : "r"(a));
}
__device__ __forceinline__ void mma_bf16(float* c, uint32_t a0, uint32_t a1,
                                         uint32_t a2, uint32_t a3,
                                         uint32_t b0, uint32_t b1) {
    asm volatile(
        "mma.sync.aligned.m16n8k16.row.col.f32.bf16.bf16.f32 "
        "{%0,%1,%2,%3}, {%4,%5,%6,%7}, {%8,%9}, {%0,%1,%2,%3};"
        : "+f"(c[0]), "+f"(c[1]), "+f"(c[2]), "+f"(c[3])
        : "r"(a0), "r"(a1), "r"(a2), "r"(a3), "r"(b0), "r"(b1));
}
__device__ __forceinline__ void mma_f16(float* c, uint32_t a0, uint32_t a1,
                                        uint32_t a2, uint32_t a3,
                                        uint32_t b0, uint32_t b1) {
    asm volatile(
        "mma.sync.aligned.m16n8k16.row.col.f32.f16.f16.f32 "
        "{%0,%1,%2,%3}, {%4,%5,%6,%7}, {%8,%9}, {%0,%1,%2,%3};"
        : "+f"(c[0]), "+f"(c[1]), "+f"(c[2]), "+f"(c[3])
        : "r"(a0), "r"(a1), "r"(a2), "r"(a3), "r"(b0), "r"(b1));
}

// smem element-offsets (2-byte units)
#define Q_ELEMS   (BM * QSTRB)          // 17408
#define KV_ARR    (BN * QSTRB)          // 8704
#define STAGE_EL  (3 * KV_ARR)          // 26112 (Kh, Kl, Vh)
#define KV0_EL    (2 * Q_ELEMS)
// total smem = (KV0_EL + 3*STAGE_EL)*2 = 226304 bytes

// ---- QK^T for one tile into sc (3-pass bf16, pass-major) ----
__device__ __forceinline__ void qk_issue(float (&sc)[8][4],
                                         uint32_t qh0, uint32_t ql0,
                                         uint32_t kh0, uint32_t kl0) {
#pragma unroll
    for (int j = 0; j < 8; j++)
#pragma unroll
        for (int c = 0; c < 4; c++) sc[j][c] = 0.0f;
#pragma unroll
    for (int ks = 0; ks < DIM / 16; ks++) {
        uint32_t dbyte = (uint32_t)(ks * 16) * 2;
        uint32_t ah[4], al[4];
        ldsm_x4(ah[0], ah[1], ah[2], ah[3], qh0 + dbyte);
        ldsm_x4(al[0], al[1], al[2], al[3], ql0 + dbyte);
        uint32_t bh[4][4], bl[4][4];
#pragma unroll
        for (int jp = 0; jp < 4; jp++) {
            uint32_t nbyte = (uint32_t)(16 * jp) * (QSTRB * 2);
            ldsm_x4(bh[jp][0], bh[jp][1], bh[jp][2], bh[jp][3], kh0 + nbyte + dbyte);
            ldsm_x4(bl[jp][0], bl[jp][1], bl[jp][2], bl[jp][3], kl0 + nbyte + dbyte);
        }
#pragma unroll
        for (int jp = 0; jp < 4; jp++) {
            mma_bf16(sc[2 * jp],     ah[0], ah[1], ah[2], ah[3], bh[jp][0], bh[jp][1]);
            mma_bf16(sc[2 * jp + 1], ah[0], ah[1], ah[2], ah[3], bh[jp][2], bh[jp][3]);
        }
#pragma unroll
        for (int jp = 0; jp < 4; jp++) {
            mma_bf16(sc[2 * jp],     ah[0], ah[1], ah[2], ah[3], bl[jp][0], bl[jp][1]);
            mma_bf16(sc[2 * jp + 1], ah[0], ah[1], ah[2], ah[3], bl[jp][2], bl[jp][3]);
        }
#pragma unroll
        for (int jp = 0; jp < 4; jp++) {
            mma_bf16(sc[2 * jp],     al[0], al[1], al[2], al[3], bh[jp][0], bh[jp][1]);
            mma_bf16(sc[2 * jp + 1], al[0], al[1], al[2], al[3], bh[jp][2], bh[jp][3]);
        }
    }
}

// ---- softmax + PV for one tile. Row sums accumulate into lf via the
//      ones-column MMA (V smem pad col 128 holds 1.0). ----
__device__ __forceinline__ void softmax_pv(float (&sc)[8][4], float (&o)[16][4],
                                           float (&lf)[4],
                                           float& m0_, float& m1_,
                                           uint32_t vh0) {
    float rmax0 = -INFINITY, rmax1 = -INFINITY;
#pragma unroll
    for (int j = 0; j < 8; j++) {
        rmax0 = fmaxf(rmax0, fmaxf(sc[j][0], sc[j][1]));
        rmax1 = fmaxf(rmax1, fmaxf(sc[j][2], sc[j][3]));
    }
#pragma unroll
    for (int off = 1; off <= 2; off <<= 1) {
        rmax0 = fmaxf(rmax0, __shfl_xor_sync(0xffffffffu, rmax0, off));
        rmax1 = fmaxf(rmax1, __shfl_xor_sync(0xffffffffu, rmax1, off));
    }
    float mnew0 = fmaxf(m0_, rmax0);
    float mnew1 = fmaxf(m1_, rmax1);
    if (mnew0 > m0_) {
        float corr = ex2(m0_ - mnew0);
        m0_ = mnew0;
#pragma unroll
        for (int j = 0; j < 16; j++) { o[j][0] *= corr; o[j][1] *= corr; }
        lf[0] *= corr; lf[1] *= corr;
    }
    if (mnew1 > m1_) {
        float corr = ex2(m1_ - mnew1);
        m1_ = mnew1;
#pragma unroll
        for (int j = 0; j < 16; j++) { o[j][2] *= corr; o[j][3] *= corr; }
        lf[2] *= corr; lf[3] *= corr;
    }

    // P fragments: subtract max (fp32), pack to half2, exponentiate 2-at-a-time
    uint32_t ph[4][4];
#pragma unroll
    for (int kk = 0; kk < 4; kk++) {
        int j0 = 2 * kk, j1 = 2 * kk + 1;
        ph[kk][0] = hex2(packh2(sc[j0][0] - mnew0, sc[j0][1] - mnew0));
        ph[kk][1] = hex2(packh2(sc[j0][2] - mnew1, sc[j0][3] - mnew1));
        ph[kk][2] = hex2(packh2(sc[j1][0] - mnew0, sc[j1][1] - mnew0));
        ph[kk][3] = hex2(packh2(sc[j1][2] - mnew1, sc[j1][3] - mnew1));
    }
#pragma unroll
    for (int kk = 0; kk < 4; kk++) {
        uint32_t sbyte = (uint32_t)(16 * kk) * (QSTRB * 2);
        // ones-column tile (V pad cols 128-135): row sums -> lf
        uint32_t c0, c1;
        ldsm_x2t(c0, c1, vh0 + sbyte + 256);
        mma_f16(lf, ph[kk][0], ph[kk][1], ph[kk][2], ph[kk][3], c0, c1);
#pragma unroll
        for (int dph = 0; dph < 4; dph++) {
            uint32_t db0 = (uint32_t)(32 * dph) * 2;
            uint32_t db1 = db0 + 16 * 2;
            uint32_t h0[4], h1[4];
            ldsm_x4t(h0[0], h0[1], h0[2], h0[3], vh0 + sbyte + db0);
            ldsm_x4t(h1[0], h1[1], h1[2], h1[3], vh0 + sbyte + db1);
            mma_f16(o[4 * dph + 0], ph[kk][0], ph[kk][1], ph[kk][2], ph[kk][3], h0[0], h0[1]);
            mma_f16(o[4 * dph + 1], ph[kk][0], ph[kk][1], ph[kk][2], ph[kk][3], h0[2], h0[3]);
            mma_f16(o[4 * dph + 2], ph[kk][0], ph[kk][1], ph[kk][2], ph[kk][3], h1[0], h1[1]);
            mma_f16(o[4 * dph + 3], ph[kk][0], ph[kk][1], ph[kk][2], ph[kk][3], h1[2], h1[3]);
        }
    }
}

__global__ __launch_bounds__(NTHREADS, 1)
void attn_kernel(float* __restrict__ out) {
    extern __shared__ __nv_bfloat16 smem[];
    const uint32_t sbase = smem_u32(smem);

    const int b    = blockIdx.y;
    const int m0   = blockIdx.x * BM;
    const int tid  = threadIdx.x;
    const int warp = tid >> 5;
    const int lane = tid & 31;
    const int g    = lane >> 2;
    const int t4   = lane & 3;

    const void* garr[3] = {g_kh, g_kl, g_vh};

    auto load_kv = [&](int t) {
        uint32_t stel = (uint32_t)(KV0_EL + (t % 3) * STAGE_EL);
#pragma unroll
        for (int it = 0; it < 12; it++) {
            int i = tid + it * NTHREADS;
            int arr = i >> 10;
            int within = i & 1023;
            int row = within >> 4;
            int chunk = within & 15;
            const char* gp = (const char*)garr[arr] +
                (((size_t)(b * SK + t * BN + row)) * DIM + chunk * 8) * 2;
            uint32_t el = stel + (uint32_t)(arr * KV_ARR + row * QSTRB + chunk * 8);
            cp16(sbase + el * 2, gp);
        }
    };

    // ---- prologue: Q hi/lo + KV(0); then KV(1) ----
    {
        const __nv_bfloat16* gq[2] = {g_qh, g_ql};
#pragma unroll
        for (int it = 0; it < 16; it++) {
            int arr = it >> 3;
            int i = tid + it * NTHREADS;
            int within = i & 2047;
            int row = within >> 4;
            int chunk = within & 15;
            const __nv_bfloat16* gp = gq[arr] +
                ((size_t)(b * LQ + m0 + row)) * DIM + chunk * 8;
            uint32_t el = (uint32_t)(arr * Q_ELEMS + row * QSTRB + chunk * 8);
            cp16(sbase + el * 2, gp);
        }
        load_kv(0);
        cp_commit();
        load_kv(1);
        cp_commit();
    }

    // ---- init V ones-column pad (cols 128..135 of each V row, all 3 stages) ----
    // cp.async only ever writes cols 0..127, so this persists across tiles.
    if (tid < 192) {
        int st = tid / 64, row = tid % 64;
        uint32_t el = (uint32_t)(KV0_EL + st * STAGE_EL + 2 * KV_ARR + row * QSTRB + 128);
        *(uint4*)((char*)smem + el * 2) = make_uint4(0x00003C00u, 0, 0, 0);
    }

    float o[16][4];
    float lf[4] = {0.0f, 0.0f, 0.0f, 0.0f};
    float scA[8][4], scB[8][4];
    float m0_ = -INFINITY, m1_ = -INFINITY;
#pragma unroll
    for (int j = 0; j < 16; j++)
#pragma unroll
        for (int c = 0; c < 4; c++) o[j][c] = 0.0f;

    const uint32_t qoff = (uint32_t)(16 * warp + (lane & 15)) * (QSTRB * 2) +
                          (uint32_t)(lane >> 4) * 16;
    const uint32_t koff = (uint32_t)((lane >> 4) * 8 + (lane & 7)) * (QSTRB * 2) +
                          (uint32_t)(lane & 8) * 2;
    const uint32_t voff = (uint32_t)((lane & 8) + (lane & 7)) * (QSTRB * 2) +
                          (uint32_t)((lane & 16) >> 1) * 2;
    const uint32_t qh0 = sbase + qoff;
    const uint32_t ql0 = sbase + Q_ELEMS * 2 + qoff;

    auto kh_of = [&](int t) {
        return sbase + (uint32_t)(KV0_EL + (t % 3) * STAGE_EL) * 2 + koff;
    };
    auto kl_of = [&](int t) {
        return sbase + (uint32_t)(KV0_EL + (t % 3) * STAGE_EL + KV_ARR) * 2 + koff;
    };
    auto vh_of = [&](int t) {
        return sbase + (uint32_t)(KV0_EL + (t % 3) * STAGE_EL + 2 * KV_ARR) * 2 + voff;
    };

    cp_wait1();          // Q + KV(0) resident
    __syncthreads();
    qk_issue(scA, qh0, ql0, kh_of(0), kl_of(0));

    for (int i = 0; i < NTILES; i += 2) {
        // ---- even tile i: QK(i+1) overlaps softmax(i) ----
        cp_wait0();
        __syncthreads();
        qk_issue(scB, qh0, ql0, kh_of(i + 1), kl_of(i + 1));
        if (i + 2 < NTILES) { load_kv(i + 2); cp_commit(); }
        softmax_pv(scA, o, lf, m0_, m1_, vh_of(i));

        // ---- odd tile i+1: QK(i+2) overlaps softmax(i+1) ----
        cp_wait0();
        __syncthreads();
        if (i + 2 < NTILES) qk_issue(scA, qh0, ql0, kh_of(i + 2), kl_of(i + 2));
        if (i + 3 < NTILES) { load_kv(i + 3); cp_commit(); }
        softmax_pv(scB, o, lf, m0_, m1_, vh_of(i + 1));
    }

    // ---- epilogue: l lives in lf[0]/lf[2] of each quad's t4==0 thread ----
    float l0v = __shfl_sync(0xffffffffu, lf[0], lane & 28);
    float l1v = __shfl_sync(0xffffffffu, lf[2], lane & 28);
    float inv0 = 1.0f / l0v;
    float inv1 = 1.0f / l1v;
    int r0 = m0 + 16 * warp + g;
    float* ob0 = out + ((size_t)b * LQ + r0) * DIM;
    float* ob1 = ob0 + 8 * DIM;
#pragma unroll
    for (int j = 0; j < 16; j++) {
        int c = 8 * j + 2 * t4;
        *(float2*)(ob0 + c) = make_float2(o[j][0] * inv0, o[j][1] * inv0);
        *(float2*)(ob1 + c) = make_float2(o[j][2] * inv1, o[j][3] * inv1);
    }
}

extern "C" void kernel_launch(void* const* d_in, const int* in_sizes, int n_in,
                              void* d_out, int out_size) {
    const float* q = (const float*)d_in[0];
    const float* k = (const float*)d_in[1];
    const float* v = (const float*)d_in[2];
    float* out = (float*)d_out;

    prep_kernel<<<(3 * BATCH * 2048) / 8, 256>>>(q, k, v);

    size_t smem_bytes = (size_t)(KV0_EL + 3 * STAGE_EL) * 2;
    cudaFuncSetAttribute(attn_kernel,
                         cudaFuncAttributeMaxDynamicSharedMemorySize,
                         (int)smem_bytes);
    dim3 grid(LQ / BM, BATCH);
    attn_kernel<<<grid, NTHREADS, smem_bytes>>>(out);
}

// round 17
// speedup vs baseline: 2.4517x; 1.1034x over previous
#include <cuda_runtime.h>
#include <cuda_bf16.h>
#include <cuda_fp16.h>
#include <math.h>
#include <stdint.h>

#define BATCH 8
#define LQ    2048
#define SK    2048
#define DIM   128
#define BM    128
#define BN    64
#define NTHREADS 320          // 256 consumer + 64 producer
#define NTILES (SK / BN)
#define QSTRB 136             // elems per smem row (DIM + 8 pad), 2B each

// Q/K bf16 hi/lo (~2^-18); V single fp16 (~2^-11, averaged out by softmax)
__device__ __nv_bfloat16 g_qh[BATCH * LQ * DIM];
__device__ __nv_bfloat16 g_ql[BATCH * LQ * DIM];
__device__ __nv_bfloat16 g_kh[BATCH * SK * DIM];
__device__ __nv_bfloat16 g_kl[BATCH * SK * DIM];
__device__ __half        g_vh[BATCH * SK * DIM];

__device__ __forceinline__ float ex2(float x) {
    float r;
    asm("ex2.approx.f32 %0, %1;" : "=f"(r) : "f"(x));
    return r;
}
__device__ __forceinline__ uint32_t hex2(uint32_t h2) {
    uint32_t r;
    asm("ex2.approx.f16x2 %0, %1;" : "=r"(r) : "r"(h2));
    return r;
}
__device__ __forceinline__ uint32_t pack2(__nv_bfloat16 a, __nv_bfloat16 b) {
    __nv_bfloat162 t; t.x = a; t.y = b;
    return *(uint32_t*)&t;
}
__device__ __forceinline__ uint32_t pack2h(__half a, __half b) {
    __half2 t; t.x = a; t.y = b;
    return *(uint32_t*)&t;
}
__device__ __forceinline__ uint32_t packh2(float x, float y) {
    __half2 t = __float22half2_rn(make_float2(x, y));
    return *(uint32_t*)&t;
}

#define QSCALE 92.33248261689366f   // 64 * log2(e)

__global__ void prep_kernel(const float* __restrict__ q,
                            const float* __restrict__ k,
                            const float* __restrict__ v) {
    int row = blockIdx.x * 8 + (threadIdx.x >> 5);
    int lane = threadIdx.x & 31;
    int kind = row / (BATCH * 2048);
    int r = row - kind * BATCH * 2048;

    const float* src = (kind == 0 ? q : kind == 1 ? k : v) + (size_t)r * DIM;
    float4 val = ((const float4*)src)[lane];
    if (kind < 2) {
        float ss = val.x * val.x + val.y * val.y + val.z * val.z + val.w * val.w;
#pragma unroll
        for (int off = 16; off > 0; off >>= 1)
            ss += __shfl_xor_sync(0xffffffffu, ss, off);
        float inv = (kind == 0 ? QSCALE : 1.0f) / fmaxf(sqrtf(ss), 1e-12f);
        val.x *= inv; val.y *= inv; val.z *= inv; val.w *= inv;
    }
    float f[4] = {val.x, val.y, val.z, val.w};

    if (kind < 2) {
        __nv_bfloat16* dh = (kind == 0 ? g_qh : g_kh) + (size_t)r * DIM;
        __nv_bfloat16* dl = (kind == 0 ? g_ql : g_kl) + (size_t)r * DIM;
        __nv_bfloat16 h[4]; float rres[4];
#pragma unroll
        for (int i = 0; i < 4; i++) {
            h[i] = __float2bfloat16_rn(f[i]);
            rres[i] = f[i] - __bfloat162float(h[i]);
        }
        uint2 hv, lv;
        hv.x = pack2(h[0], h[1]);
        hv.y = pack2(h[2], h[3]);
        lv.x = pack2(__float2bfloat16_rn(rres[0]), __float2bfloat16_rn(rres[1]));
        lv.y = pack2(__float2bfloat16_rn(rres[2]), __float2bfloat16_rn(rres[3]));
        *(uint2*)(dh + lane * 4) = hv;
        *(uint2*)(dl + lane * 4) = lv;
    } else {
        __half* dh = g_vh + (size_t)r * DIM;
        uint2 hv;
        hv.x = pack2h(__float2half_rn(f[0]), __float2half_rn(f[1]));
        hv.y = pack2h(__float2half_rn(f[2]), __float2half_rn(f[3]));
        *(uint2*)(dh + lane * 4) = hv;
    }
}

__device__ __forceinline__ uint32_t smem_u32(const void* p) {
    return (uint32_t)__cvta_generic_to_shared(p);
}
__device__ __forceinline__ void cp16(uint32_t daddr, const void* g) {
    asm volatile("cp.async.cg.shared.global [%0], [%1], 16;" :: "r"(daddr), "l"(g));
}
__device__ __forceinline__ void cp_commit() {
    asm volatile("cp.async.commit_group;" ::: "memory");
}
__device__ __forceinline__ void cp_wait0() {
    asm volatile("cp.async.wait_group 0;" ::: "memory");
}
__device__ __forceinline__ void cp_wait1() {
    asm volatile("cp.async.wait_group 1;" ::: "memory");
}
#define MBAR_INIT(mb, n) asm volatile("mbarrier.init.shared.b64 [%0], %1;" :: "r"(mb), "r"(n) : "memory")
#define MBAR_ARRIVE(mb)  asm volatile("mbarrier.arrive.shared.b64 _, [%0];" :: "r"(mb) : "memory")
__device__ __forceinline__ void mbar_wait(uint32_t mb, uint32_t parity) {
    asm volatile(
        "{\n\t.reg .pred P1;\n\t"
        "WL_%=:\n\t"
        "mbarrier.try_wait.parity.acquire.cta.shared::cta.b64 P1, [%0], %1, 0x989680;\n\t"
        "@P1 bra.uni WD_%=;\n\t"
        "bra.uni WL_%=;\n\t"
        "WD_%=:\n\t}"
        :: "r"(mb), "r"(parity) : "memory");
}
__device__ __forceinline__ void ldsm_x4(uint32_t& r0, uint32_t& r1,
                                        uint32_t& r2, uint32_t& r3, uint32_t a) {
    asm volatile("ldmatrix.sync.aligned.m8n8.x4.shared.b16 {%0,%1,%2,%3}, [%4];"
                 : "=r"(r0), "=r"(r1), "=r"(r2), "=r"(r3) : "r"(a));
}
__device__ __forceinline__ void ldsm_x4t(uint32_t& r0, uint32_t& r1,
                                         uint32_t& r2, uint32_t& r3, uint32_t a) {
    asm volatile("ldmatrix.sync.aligned.m8n8.x4.trans.shared.b16 {%0,%1,%2,%3}, [%4];"
                 : "=r"(r0), "=r"(r1), "=r"(r2), "=r"(r3) : "r"(a));
}
__device__ __forceinline__ void ldsm_x2t(uint32_t& r0, uint32_t& r1, uint32_t a) {
    asm volatile("ldmatrix.sync.aligned.m8n8.x2.trans.shared.b16 {%0,%1}, [%2];"
                 : "=r"(r0), "=r"(r1) : "r"(a));
}
__device__ __forceinline__ void mma_bf16(float* c, uint32_t a0, uint32_t a1,
                                         uint32_t a2, uint32_t a3,
                                         uint32_t b0, uint32_t b1) {
    asm volatile(
        "mma.sync.aligned.m16n8k16.row.col.f32.bf16.bf16.f32 "
        "{%0,%1,%2,%3}, {%4,%5,%6,%7}, {%8,%9}, {%0,%1,%2,%3};"
        : "+f"(c[0]), "+f"(c[1]), "+f"(c[2]), "+f"(c[3])
        : "r"(a0), "r"(a1), "r"(a2), "r"(a3), "r"(b0), "r"(b1));
}
__device__ __forceinline__ void mma_f16(float* c, uint32_t a0, uint32_t a1,
                                        uint32_t a2, uint32_t a3,
                                        uint32_t b0, uint32_t b1) {
    asm volatile(
        "mma.sync.aligned.m16n8k16.row.col.f32.f16.f16.f32 "
        "{%0,%1,%2,%3}, {%4,%5,%6,%7}, {%8,%9}, {%0,%1,%2,%3};"
        : "+f"(c[0]), "+f"(c[1]), "+f"(c[2]), "+f"(c[3])
        : "r"(a0), "r"(a1), "r"(a2), "r"(a3), "r"(b0), "r"(b1));
}

// smem element-offsets (2-byte units)
#define MB_EL     32                       // 64B for 3 full + 3 empty mbarriers
#define Q_ELEMS   (BM * QSTRB)             // 17408
#define KV_ARR    (BN * QSTRB)             // 8704
#define STAGE_EL  (3 * KV_ARR)             // 26112 (Kh, Kl, Vh)
#define Q0_EL     MB_EL
#define KV0_EL    (MB_EL + 2 * Q_ELEMS)
// total smem = (KV0_EL + 3*STAGE_EL)*2 = 226368 bytes
#define MB_FULL(s)  ((uint32_t)((s) * 16))
#define MB_EMPTY(s) ((uint32_t)((s) * 16 + 8))

// ---- QK^T for one tile into sc (3-pass bf16, pass-major) ----
__device__ __forceinline__ void qk_issue(float (&sc)[8][4],
                                         uint32_t qh0, uint32_t ql0,
                                         uint32_t kh0, uint32_t kl0) {
#pragma unroll
    for (int j = 0; j < 8; j++)
#pragma unroll
        for (int c = 0; c < 4; c++) sc[j][c] = 0.0f;
#pragma unroll
    for (int ks = 0; ks < DIM / 16; ks++) {
        uint32_t dbyte = (uint32_t)(ks * 16) * 2;
        uint32_t ah[4], al[4];
        ldsm_x4(ah[0], ah[1], ah[2], ah[3], qh0 + dbyte);
        ldsm_x4(al[0], al[1], al[2], al[3], ql0 + dbyte);
        uint32_t bh[4][4], bl[4][4];
#pragma unroll
        for (int jp = 0; jp < 4; jp++) {
            uint32_t nbyte = (uint32_t)(16 * jp) * (QSTRB * 2);
            ldsm_x4(bh[jp][0], bh[jp][1], bh[jp][2], bh[jp][3], kh0 + nbyte + dbyte);
            ldsm_x4(bl[jp][0], bl[jp][1], bl[jp][2], bl[jp][3], kl0 + nbyte + dbyte);
        }
#pragma unroll
        for (int jp = 0; jp < 4; jp++) {
            mma_bf16(sc[2 * jp],     ah[0], ah[1], ah[2], ah[3], bh[jp][0], bh[jp][1]);
            mma_bf16(sc[2 * jp + 1], ah[0], ah[1], ah[2], ah[3], bh[jp][2], bh[jp][3]);
        }
#pragma unroll
        for (int jp = 0; jp < 4; jp++) {
            mma_bf16(sc[2 * jp],     ah[0], ah[1], ah[2], ah[3], bl[jp][0], bl[jp][1]);
            mma_bf16(sc[2 * jp + 1], ah[0], ah[1], ah[2], ah[3], bl[jp][2], bl[jp][3]);
        }
#pragma unroll
        for (int jp = 0; jp < 4; jp++) {
            mma_bf16(sc[2 * jp],     al[0], al[1], al[2], al[3], bh[jp][0], bh[jp][1]);
            mma_bf16(sc[2 * jp + 1], al[0], al[1], al[2], al[3], bh[jp][2], bh[jp][3]);
        }
    }
}

// ---- softmax + PV for one tile (ones-column MMA row sums into lf) ----
__device__ __forceinline__ void softmax_pv(float (&sc)[8][4], float (&o)[16][4],
                                           float (&lf)[4],
                                           float& m0_, float& m1_,
                                           uint32_t vh0) {
    float rmax0 = -INFINITY, rmax1 = -INFINITY;
#pragma unroll
    for (int j = 0; j < 8; j++) {
        rmax0 = fmaxf(rmax0, fmaxf(sc[j][0], sc[j][1]));
        rmax1 = fmaxf(rmax1, fmaxf(sc[j][2], sc[j][3]));
    }
#pragma unroll
    for (int off = 1; off <= 2; off <<= 1) {
        rmax0 = fmaxf(rmax0, __shfl_xor_sync(0xffffffffu, rmax0, off));
        rmax1 = fmaxf(rmax1, __shfl_xor_sync(0xffffffffu, rmax1, off));
    }
    float mnew0 = fmaxf(m0_, rmax0);
    float mnew1 = fmaxf(m1_, rmax1);
    if (mnew0 > m0_) {
        float corr = ex2(m0_ - mnew0);
        m0_ = mnew0;
#pragma unroll
        for (int j = 0; j < 16; j++) { o[j][0] *= corr; o[j][1] *= corr; }
        lf[0] *= corr; lf[1] *= corr;
    }
    if (mnew1 > m1_) {
        float corr = ex2(m1_ - mnew1);
        m1_ = mnew1;
#pragma unroll
        for (int j = 0; j < 16; j++) { o[j][2] *= corr; o[j][3] *= corr; }
        lf[2] *= corr; lf[3] *= corr;
    }

    uint32_t ph[4][4];
#pragma unroll
    for (int kk = 0; kk < 4; kk++) {
        int j0 = 2 * kk, j1 = 2 * kk + 1;
        ph[kk][0] = hex2(packh2(sc[j0][0] - mnew0, sc[j0][1] - mnew0));
        ph[kk][1] = hex2(packh2(sc[j0][2] - mnew1, sc[j0][3] - mnew1));
        ph[kk][2] = hex2(packh2(sc[j1][0] - mnew0, sc[j1][1] - mnew0));
        ph[kk][3] = hex2(packh2(sc[j1][2] - mnew1, sc[j1][3] - mnew1));
    }
#pragma unroll
    for (int kk = 0; kk < 4; kk++) {
        uint32_t sbyte = (uint32_t)(16 * kk) * (QSTRB * 2);
        uint32_t c0, c1;
        ldsm_x2t(c0, c1, vh0 + sbyte + 256);
        mma_f16(lf, ph[kk][0], ph[kk][1], ph[kk][2], ph[kk][3], c0, c1);
#pragma unroll
        for (int dph = 0; dph < 4; dph++) {
            uint32_t db0 = (uint32_t)(32 * dph) * 2;
            uint32_t db1 = db0 + 16 * 2;
            uint32_t h0[4], h1[4];
            ldsm_x4t(h0[0], h0[1], h0[2], h0[3], vh0 + sbyte + db0);
            ldsm_x4t(h1[0], h1[1], h1[2], h1[3], vh0 + sbyte + db1);
            mma_f16(o[4 * dph + 0], ph[kk][0], ph[kk][1], ph[kk][2], ph[kk][3], h0[0], h0[1]);
            mma_f16(o[4 * dph + 1], ph[kk][0], ph[kk][1], ph[kk][2], ph[kk][3], h0[2], h0[3]);
            mma_f16(o[4 * dph + 2], ph[kk][0], ph[kk][1], ph[kk][2], ph[kk][3], h1[0], h1[1]);
            mma_f16(o[4 * dph + 3], ph[kk][0], ph[kk][1], ph[kk][2], ph[kk][3], h1[2], h1[3]);
        }
    }
}

__global__ __launch_bounds__(NTHREADS, 1)
void attn_kernel(float* __restrict__ out) {
    extern __shared__ __nv_bfloat16 smem[];
    const uint32_t sbase = smem_u32(smem);

    const int b    = blockIdx.y;
    const int m0   = blockIdx.x * BM;
    const int tid  = threadIdx.x;
    const int warp = tid >> 5;
    const int lane = tid & 31;
    const int g    = lane >> 2;
    const int t4   = lane & 3;
    const bool is_consumer = tid < 256;

    // ---- startup (before the one global barrier) ----
    if (is_consumer) {
        // consumers async-load Q hi/lo
        const __nv_bfloat16* gq[2] = {g_qh, g_ql};
#pragma unroll
        for (int it = 0; it < 16; it++) {
            int arr = it >> 3;
            int i = tid + it * 256;
            int within = i & 2047;
            int row = within >> 4;
            int chunk = within & 15;
            const __nv_bfloat16* gp = gq[arr] +
                ((size_t)(b * LQ + m0 + row)) * DIM + chunk * 8;
            uint32_t el = (uint32_t)(Q0_EL + arr * Q_ELEMS + row * QSTRB + chunk * 8);
            cp16(sbase + el * 2, gp);
        }
        cp_commit();
        // ones-column pad init (cols 128..135 of each V row, all 3 stages)
        if (tid < 192) {
            int st = tid / 64, row = tid % 64;
            uint32_t el = (uint32_t)(KV0_EL + st * STAGE_EL + 2 * KV_ARR + row * QSTRB + 128);
            *(uint4*)((char*)smem + el * 2) = make_uint4(0x00003C00u, 0, 0, 0);
        }
        if (tid == 0) {
#pragma unroll
            for (int s = 0; s < 3; s++) {
                MBAR_INIT(sbase + MB_FULL(s), 64);   // 64 producer threads
                MBAR_INIT(sbase + MB_EMPTY(s), 8);   // 8 consumer warps
            }
        }
    }
    __syncthreads();   // mbarriers + ones-init visible to everyone

    if (!is_consumer) {
        // ================= producer warps =================
        const int ptid = tid - 256;                    // 0..63
        const void* garr[3] = {g_kh, g_kl, g_vh};
        for (int t = 0; t < NTILES; t++) {
            int s = t % 3, r = t / 3;
            if (t >= 3) mbar_wait(sbase + MB_EMPTY(s), (uint32_t)((r - 1) & 1));
            uint32_t stel = (uint32_t)(KV0_EL + s * STAGE_EL);
#pragma unroll
            for (int it = 0; it < 48; it++) {
                int i = ptid + it * 64;
                int arr = i >> 10;
                int within = i & 1023;
                int row = within >> 4;
                int chunk = within & 15;
                const char* gp = (const char*)garr[arr] +
                    (((size_t)(b * SK + t * BN + row)) * DIM + chunk * 8) * 2;
                uint32_t el = stel + (uint32_t)(arr * KV_ARR + row * QSTRB + chunk * 8);
                cp16(sbase + el * 2, gp);
            }
            cp_commit();
            if (t >= 1) {          // keep 2 groups in flight
                cp_wait1();
                MBAR_ARRIVE(sbase + MB_FULL((t - 1) % 3));
            }
        }
        cp_wait0();
        MBAR_ARRIVE(sbase + MB_FULL((NTILES - 1) % 3));
        return;
    }

    // ================= consumer warps =================
    float o[16][4];
    float lf[4] = {0.0f, 0.0f, 0.0f, 0.0f};
    float sc[8][4];
    float m0_ = -INFINITY, m1_ = -INFINITY;
#pragma unroll
    for (int j = 0; j < 16; j++)
#pragma unroll
        for (int c = 0; c < 4; c++) o[j][c] = 0.0f;

    const uint32_t qoff = (uint32_t)(16 * warp + (lane & 15)) * (QSTRB * 2) +
                          (uint32_t)(lane >> 4) * 16;
    const uint32_t koff = (uint32_t)((lane >> 4) * 8 + (lane & 7)) * (QSTRB * 2) +
                          (uint32_t)(lane & 8) * 2;
    const uint32_t voff = (uint32_t)((lane & 8) + (lane & 7)) * (QSTRB * 2) +
                          (uint32_t)((lane & 16) >> 1) * 2;
    const uint32_t qh0 = sbase + Q0_EL * 2 + qoff;
    const uint32_t ql0 = sbase + (Q0_EL + Q_ELEMS) * 2 + qoff;

    cp_wait0();                               // own Q copies done
    asm volatile("bar.sync 1, 256;" ::: "memory");   // Q visible to all consumers

    for (int t = 0; t < NTILES; t++) {
        int s = t % 3, r = t / 3;
        uint32_t stb = sbase + (uint32_t)(KV0_EL + s * STAGE_EL) * 2;
        mbar_wait(sbase + MB_FULL(s), (uint32_t)(r & 1));
        qk_issue(sc, qh0, ql0, stb + koff, stb + KV_ARR * 2 + koff);
        softmax_pv(sc, o, lf, m0_, m1_, stb + 2 * KV_ARR * 2 + voff);
        if (lane == 0) MBAR_ARRIVE(sbase + MB_EMPTY(s));
    }

    // ---- epilogue ----
    float l0v = __shfl_sync(0xffffffffu, lf[0], lane & 28);
    float l1v = __shfl_sync(0xffffffffu, lf[2], lane & 28);
    float inv0 = 1.0f / l0v;
    float inv1 = 1.0f / l1v;
    int r0 = m0 + 16 * warp + g;
    float* ob0 = out + ((size_t)b * LQ + r0) * DIM;
    float* ob1 = ob0 + 8 * DIM;
#pragma unroll
    for (int j = 0; j < 16; j++) {
        int c = 8 * j + 2 * t4;
        *(float2*)(ob0 + c) = make_float2(o[j][0] * inv0, o[j][1] * inv0);
        *(float2*)(ob1 + c) = make_float2(o[j][2] * inv1, o[j][3] * inv1);
    }
}

extern "C" void kernel_launch(void* const* d_in, const int* in_sizes, int n_in,
                              void* d_out, int out_size) {
    const float* q = (const float*)d_in[0];
    const float* k = (const float*)d_in[1];
    const float* v = (const float*)d_in[2];
    float* out = (float*)d_out;

    prep_kernel<<<(3 * BATCH * 2048) / 8, 256>>>(q, k, v);

    size_t smem_bytes = (size_t)(KV0_EL + 3 * STAGE_EL) * 2;
    cudaFuncSetAttribute(attn_kernel,
                         cudaFuncAttributeMaxDynamicSharedMemorySize,
                         (int)smem_bytes);
    dim3 grid(LQ / BM, BATCH);
    attn_kernel<<<grid, NTHREADS, smem_bytes>>>(out);
}